// round 11
// baseline (speedup 1.0000x reference)
#include <cuda_runtime.h>

// ---------------------------------------------------------------------------
// DFMNET: 2-layer LSTM (B=2048, T=256, I=64, H=128) + 6-layer MLP head.
// Persistent CTA per 16 batch rows runs all 256 timesteps.
// R11: thread = 16 gate cols x 8 rows over K/4 (256 threads = 32 col-strips
// x 2 row-groups x 4 k-groups). Halves LDS broadcast return vs R10
// (broadcast LDS.128 = 4 wavefronts; return scales with rows*K per thread)
// -> L1 ~16.4K wf vs 28.7K FMA cyc per step: FMA finally binds with margin.
// Weights [chunk][j=0..7][cs=0..31][float4], fully warp-coalesced LDG.128,
// depth-1 double-buffered with padded tail. f32x2 FFMA throughout.
// ---------------------------------------------------------------------------

#define T_SEQ    256
#define I_IN     64
#define H_HID    128
#define ROWS     16            // batch rows per CTA
#define NTHREADS 256
#define KROWS    320           // xh rows: [x(64) | h1(128) | h2(128)]
#define GSTR     516           // gate-buffer row stride (floats)
#define BSTR     (ROWS * GSTR) // per-partial-buffer stride (floats)

typedef unsigned long long ull;

// Weights: [chunk][j=0..7][cs=0..31][4 floats]. For col-strip cs (cols
// cs*16..cs*16+15), float4 j = (c_{2j} k0, c_{2j} k1, c_{2j+1} k0, c_{2j+1} k1),
// k = 2c, 2c+1. +1 zero-padded chunk so the depth-1 prefetch never branches.
__device__ __align__(16) float g_Wt1[(96 + 1) * 1024];    // K=192 -> 96 chunks
__device__ __align__(16) float g_Wt2[(128 + 1) * 1024];   // K=256 -> 128 chunks
__device__ float g_b1[512];
__device__ float g_b2[512];

// ---- packed fp32x2 helpers ----
__device__ __forceinline__ ull fma2(ull a, ull b, ull c) {
    ull d;
    asm("fma.rn.f32x2 %0, %1, %2, %3;" : "=l"(d) : "l"(a), "l"(b), "l"(c));
    return d;
}
__device__ __forceinline__ void unpack2(ull v, float& lo, float& hi) {
    unsigned a, b;
    asm("mov.b64 {%0, %1}, %2;" : "=r"(a), "=r"(b) : "l"(v));
    lo = __uint_as_float(a); hi = __uint_as_float(b);
}
__device__ __forceinline__ ull dup2(float w) {
    ull r; unsigned u = __float_as_uint(w);
    asm("mov.b64 %0, {%1, %1};" : "=l"(r) : "r"(u));
    return r;
}

__device__ __forceinline__ float sigf(float v) {
    return __fdividef(1.f, 1.f + __expf(-v));
}
__device__ __forceinline__ float tanhf_fast(float v) {
    float z = fminf(fmaxf(v, -15.f), 15.f);
    float e = __expf(-2.f * z);
    return __fdividef(1.f - e, 1.f + e);
}

// ---------------------------------------------------------------------------
// Weight repack into the coalesced [chunk][j][cs][f] layout.
//   e = c*1024 + j*128 + cs*4 + f ;  ci = 2j + (f>>1), s = f&1
//   g = cs*16 + ci ; k = 2c + s
// ---------------------------------------------------------------------------
__global__ void prep_kernel(const float* __restrict__ Wih1, const float* __restrict__ Whh1,
                            const float* __restrict__ bih1, const float* __restrict__ bhh1,
                            const float* __restrict__ Wih2, const float* __restrict__ Whh2,
                            const float* __restrict__ bih2, const float* __restrict__ bhh2)
{
    int tid = blockIdx.x * blockDim.x + threadIdx.x;
    int stride = gridDim.x * blockDim.x;
    if (tid < 512) {
        g_b1[tid] = bih1[tid] + bhh1[tid];
        g_b2[tid] = bih2[tid] + bhh2[tid];
    }
    for (int e = tid; e < 97 * 1024; e += stride) {
        int c = e >> 10, r = e & 1023;
        int j = r >> 7, cs = (r >> 2) & 31, f = r & 3;
        int ci = 2 * j + (f >> 1), s = f & 1;
        int g = cs * 16 + ci;
        int k = 2 * c + s;
        float w = 0.f;
        if (k < 192) w = (k < 64) ? Wih1[g * 64 + k] : Whh1[g * 128 + (k - 64)];
        g_Wt1[e] = w;
    }
    for (int e = tid; e < 129 * 1024; e += stride) {
        int c = e >> 10, r = e & 1023;
        int j = r >> 7, cs = (r >> 2) & 31, f = r & 3;
        int ci = 2 * j + (f >> 1), s = f & 1;
        int g = cs * 16 + ci;
        int k = 2 * c + s;
        float w = 0.f;
        if (k < 256) w = (k < 128) ? Wih2[g * 128 + k] : Whh2[g * 128 + (k - 128)];
        g_Wt2[e] = w;
    }
}

// ---------------------------------------------------------------------------
// Partial gate GEMM over chunk range [cb, cb+nc):
//   gbuf[16][GSTR] = (bias?) + xh-slice @ Wt-slice for this thread's
//   16 cols (cs*16..cs*16+15) x 8 rows (rg*8..rg*8+7).
// acc[ci][rp] = f32x2 over rows (rg*8+2rp, rg*8+2rp+1), col cs*16+ci.
// Per chunk/thread: 8 COALESCED LDG.128 (prefetched depth-1), 4 broadcast
// LDS.128, 32 dup MOVs (alu pipe), 128 FFMA2 (the binder).
// ---------------------------------------------------------------------------
__device__ __forceinline__ void gemm_gates(const float* __restrict__ Wt,
                                           const float* __restrict__ bias,
                                           const float* __restrict__ xh,   // [k][16]
                                           float* __restrict__ gbuf,       // [16][GSTR]
                                           int cb, int nc, int rg, int cs, bool add_bias)
{
    const int c0 = cs * 16;
    ull acc[16][4];
    if (add_bias) {
#pragma unroll
        for (int ci = 0; ci < 16; ci++) {
            ull b = dup2(bias[c0 + ci]);
#pragma unroll
            for (int rp = 0; rp < 4; rp++) acc[ci][rp] = b;
        }
    } else {
#pragma unroll
        for (int ci = 0; ci < 16; ci++)
#pragma unroll
            for (int rp = 0; rp < 4; rp++) acc[ci][rp] = 0ull;
    }

    // coalesced: lane cs reads float4 at (chunk base) + j*32 float4s + cs
    const float4* Wp = (const float4*)Wt + cb * 256 + cs;
    float4 wc[8];
#pragma unroll
    for (int j = 0; j < 8; j++) wc[j] = Wp[j * 32];
    const ulonglong2* xq = (const ulonglong2*)(xh + cb * 32 + rg * 8);

#pragma unroll 1
    for (int c = 0; c < nc; c++) {
        // prefetch next chunk's weights (padded tail: always safe)
        float4 wn[8];
#pragma unroll
        for (int j = 0; j < 8; j++) wn[j] = Wp[256 + j * 32];
        Wp += 256;
        // this thread's 8 rows for k=2c (q0,q1) and k=2c+1 (q2,q3); broadcast
        ulonglong2 q0 = xq[0], q1 = xq[1];
        ulonglong2 q2 = xq[4], q3 = xq[5];
        xq += 8;

#pragma unroll
        for (int j = 0; j < 8; j++) {
            ull t;
            t = dup2(wc[j].x);   // col 2j, k even
            acc[2*j][0] = fma2(t, q0.x, acc[2*j][0]);
            acc[2*j][1] = fma2(t, q0.y, acc[2*j][1]);
            acc[2*j][2] = fma2(t, q1.x, acc[2*j][2]);
            acc[2*j][3] = fma2(t, q1.y, acc[2*j][3]);
            t = dup2(wc[j].y);   // col 2j, k odd
            acc[2*j][0] = fma2(t, q2.x, acc[2*j][0]);
            acc[2*j][1] = fma2(t, q2.y, acc[2*j][1]);
            acc[2*j][2] = fma2(t, q3.x, acc[2*j][2]);
            acc[2*j][3] = fma2(t, q3.y, acc[2*j][3]);
            t = dup2(wc[j].z);   // col 2j+1, k even
            acc[2*j+1][0] = fma2(t, q0.x, acc[2*j+1][0]);
            acc[2*j+1][1] = fma2(t, q0.y, acc[2*j+1][1]);
            acc[2*j+1][2] = fma2(t, q1.x, acc[2*j+1][2]);
            acc[2*j+1][3] = fma2(t, q1.y, acc[2*j+1][3]);
            t = dup2(wc[j].w);   // col 2j+1, k odd
            acc[2*j+1][0] = fma2(t, q2.x, acc[2*j+1][0]);
            acc[2*j+1][1] = fma2(t, q2.y, acc[2*j+1][1]);
            acc[2*j+1][2] = fma2(t, q3.x, acc[2*j+1][2]);
            acc[2*j+1][3] = fma2(t, q3.y, acc[2*j+1][3]);
        }
#pragma unroll
        for (int j = 0; j < 8; j++) wc[j] = wn[j];
    }

    // write 8 rows x 16 cols: four float4 STS per row-pair element
#pragma unroll
    for (int rp = 0; rp < 4; rp++) {
        float la[16], ha[16];
#pragma unroll
        for (int ci = 0; ci < 16; ci++) unpack2(acc[ci][rp], la[ci], ha[ci]);
        int row0 = rg * 8 + 2 * rp;
        float* d0 = gbuf + row0 * GSTR + c0;
        float* d1 = d0 + GSTR;
#pragma unroll
        for (int v = 0; v < 4; v++) {
            *(float4*)(d0 + 4 * v) = make_float4(la[4*v], la[4*v+1], la[4*v+2], la[4*v+3]);
            *(float4*)(d1 + 4 * v) = make_float4(ha[4*v], ha[4*v+1], ha[4*v+2], ha[4*v+3]);
        }
    }
}

// Small MLP layer over the CTA's 16 rows (head only; negligible cost)
__device__ __forceinline__ void mlp_layer(const float* __restrict__ vin, int Din,
                                          const float* __restrict__ W, const float* __restrict__ b,
                                          float* __restrict__ vout, int Dout, bool relu, int tid)
{
    for (int e = tid; e < ROWS * Dout; e += NTHREADS) {
        int r = e / Dout, o = e - r * Dout;
        const float* w = W + o * Din;
        const float* vi = vin + r * Din;
        float s = b[o];
        for (int i = 0; i < Din; i += 4) {
            s += w[i] * vi[i] + w[i + 1] * vi[i + 1] + w[i + 2] * vi[i + 2] + w[i + 3] * vi[i + 3];
        }
        vout[e] = relu ? fmaxf(s, 0.f) : s;
    }
    __syncthreads();
}

// ---------------------------------------------------------------------------
__global__ void __launch_bounds__(NTHREADS, 1)
dfmnet_main(const float* __restrict__ x,
            const float* __restrict__ Wk0, const float* __restrict__ bk0,
            const float* __restrict__ Wk1, const float* __restrict__ bk1,
            const float* __restrict__ Wk2, const float* __restrict__ bk2,
            const float* __restrict__ Wk3, const float* __restrict__ bk3,
            const float* __restrict__ Wk4, const float* __restrict__ bk4,
            const float* __restrict__ Wk5, const float* __restrict__ bk5,
            float* __restrict__ out, int Bn)
{
    extern __shared__ float sm[];
    float* xh    = sm;                    // [KROWS][16]
    float* gates = sm + KROWS * ROWS;     // 4 partial buffers [16][GSTR] each

    const int tid = threadIdx.x;
    const int kg  = tid >> 6;             // k-group 0..3 (2 warps each)
    const int rg  = (tid >> 5) & 1;       // row-group 0/1 (uniform per warp)
    const int cs  = tid & 31;             // col-strip: cols cs*16..cs*16+15
    const int b0  = blockIdx.x * ROWS;

    for (int e = tid; e < KROWS * ROWS; e += NTHREADS) xh[e] = 0.f;
    float c1r[8], c2r[8];
#pragma unroll
    for (int p = 0; p < 8; p++) { c1r[p] = 0.f; c2r[p] = 0.f; }
    __syncthreads();

    const float* xbase = x + (size_t)b0 * T_SEQ * I_IN;
    float* mybuf = gates + kg * BSTR;

    for (int t = 0; t < T_SEQ; t++) {
        // load x_t (16 rows x 64) transposed into xh rows [0,64)
#pragma unroll
        for (int q = 0; q < 4; q++) {
            int e = tid + q * NTHREADS;            // 0..1023
            int r = e >> 6, k = e & 63;
            xh[k * ROWS + r] = xbase[(size_t)r * (T_SEQ * I_IN) + t * I_IN + k];
        }
        __syncthreads();

        // layer 1: K=192 -> 96 chunks, 24 per k-group
        gemm_gates(g_Wt1, g_b1, xh, mybuf, kg * 24, 24, rg, cs, kg == 0);
        __syncthreads();

        // layer 1 activation: h1 -> xh rows [64,192); sum 4 partials
#pragma unroll
        for (int p = 0; p < 8; p++) {
            int idx = tid + p * NTHREADS;          // 0..2047
            int j = idx >> 4, r = idx & 15;
            const float* gb = gates + r * GSTR + j;
            float pi = gb[0]   + gb[BSTR]       + gb[2 * BSTR]       + gb[3 * BSTR];
            float pf = gb[128] + gb[BSTR + 128] + gb[2 * BSTR + 128] + gb[3 * BSTR + 128];
            float pg = gb[256] + gb[BSTR + 256] + gb[2 * BSTR + 256] + gb[3 * BSTR + 256];
            float po = gb[384] + gb[BSTR + 384] + gb[2 * BSTR + 384] + gb[3 * BSTR + 384];
            float iv = sigf(pi);
            float fv = sigf(pf);
            float gv = tanhf_fast(pg);
            float ov = sigf(po);
            float c = fv * c1r[p] + iv * gv;
            c1r[p] = c;
            xh[(64 + j) * ROWS + r] = ov * tanhf_fast(c);
        }
        __syncthreads();

        // layer 2: K=256 -> 128 chunks, 32 per k-group; xh rows [64,320)
        gemm_gates(g_Wt2, g_b2, xh + 64 * ROWS, mybuf, kg * 32, 32, rg, cs, kg == 0);
        __syncthreads();

        // layer 2 activation: h2 -> xh rows [192,320)
#pragma unroll
        for (int p = 0; p < 8; p++) {
            int idx = tid + p * NTHREADS;
            int j = idx >> 4, r = idx & 15;
            const float* gb = gates + r * GSTR + j;
            float pi = gb[0]   + gb[BSTR]       + gb[2 * BSTR]       + gb[3 * BSTR];
            float pf = gb[128] + gb[BSTR + 128] + gb[2 * BSTR + 128] + gb[3 * BSTR + 128];
            float pg = gb[256] + gb[BSTR + 256] + gb[2 * BSTR + 256] + gb[3 * BSTR + 256];
            float po = gb[384] + gb[BSTR + 384] + gb[2 * BSTR + 384] + gb[3 * BSTR + 384];
            float iv = sigf(pi);
            float fv = sigf(pf);
            float gv = tanhf_fast(pg);
            float ov = sigf(po);
            float c = fv * c2r[p] + iv * gv;
            c2r[p] = c;
            xh[(192 + j) * ROWS + r] = ov * tanhf_fast(c);
        }
        // next iter's x-load writes disjoint smem; its __syncthreads orders
        // these h2 writes (and this phase's gates reads) before reuse.
    }
    __syncthreads();

    // ---- outputs: tuple (y, h2, r) flattened ----
    float* out_y  = out;                              // [Bn][64]
    float* out_h2 = out + (size_t)Bn * 64;            // [Bn][128]
    float* out_r  = out + (size_t)Bn * 192;           // [Bn][192]

    float* va = gates;              // [16][192]
    float* vb = gates + ROWS * 192; // [16][128]
    float* vc = vb + ROWS * 128;    // [16][128]
    for (int e = tid; e < ROWS * 192; e += NTHREADS) {
        int r = e / 192, j = e - r * 192;
        float v = (j < 128) ? xh[(192 + j) * ROWS + r] : xh[(j - 128) * ROWS + r];
        va[e] = v;
        out_r[(size_t)(b0 + r) * 192 + j] = v;
        if (j < 128) out_h2[(size_t)(b0 + r) * 128 + j] = v;
    }
    __syncthreads();

    mlp_layer(va, 192, Wk0, bk0, vb, 128, true, tid);
    mlp_layer(vb, 128, Wk1, bk1, vc, 128, true, tid);
    mlp_layer(vc, 128, Wk2, bk2, vb, 128, true, tid);
    mlp_layer(vb, 128, Wk3, bk3, vc, 128, true, tid);
    mlp_layer(vc, 128, Wk4, bk4, vb, 128, true, tid);

    for (int e = tid; e < ROWS * 64; e += NTHREADS) {
        int r = e >> 6, o = e & 63;
        const float* w = Wk5 + o * 128;
        const float* vi = vb + r * 128;
        float s = bk5[o];
        for (int i = 0; i < 128; i += 4) {
            s += w[i] * vi[i] + w[i + 1] * vi[i + 1] + w[i + 2] * vi[i + 2] + w[i + 3] * vi[i + 3];
        }
        out_y[(size_t)(b0 + r) * 64 + o] = s;
    }
}

// ---------------------------------------------------------------------------
extern "C" void kernel_launch(void* const* d_in, const int* in_sizes, int n_in,
                              void* d_out, int out_size)
{
    const float* x    = (const float*)d_in[0];
    const float* Wih1 = (const float*)d_in[1];
    const float* Whh1 = (const float*)d_in[2];
    const float* bih1 = (const float*)d_in[3];
    const float* bhh1 = (const float*)d_in[4];
    const float* Wih2 = (const float*)d_in[5];
    const float* Whh2 = (const float*)d_in[6];
    const float* bih2 = (const float*)d_in[7];
    const float* bhh2 = (const float*)d_in[8];
    const float* Wk0 = (const float*)d_in[9];   const float* bk0 = (const float*)d_in[10];
    const float* Wk1 = (const float*)d_in[11];  const float* bk1 = (const float*)d_in[12];
    const float* Wk2 = (const float*)d_in[13];  const float* bk2 = (const float*)d_in[14];
    const float* Wk3 = (const float*)d_in[15];  const float* bk3 = (const float*)d_in[16];
    const float* Wk4 = (const float*)d_in[17];  const float* bk4 = (const float*)d_in[18];
    const float* Wk5 = (const float*)d_in[19];  const float* bk5 = (const float*)d_in[20];

    int Bn = in_sizes[0] / (T_SEQ * I_IN);
    int smem_bytes = (KROWS * ROWS + 4 * ROWS * GSTR) * (int)sizeof(float);  // 152576 B

    cudaFuncSetAttribute(dfmnet_main, cudaFuncAttributeMaxDynamicSharedMemorySize, smem_bytes);

    prep_kernel<<<208, 256>>>(Wih1, Whh1, bih1, bhh1, Wih2, Whh2, bih2, bhh2);
    dfmnet_main<<<Bn / ROWS, NTHREADS, smem_bytes>>>(
        x, Wk0, bk0, Wk1, bk1, Wk2, bk2, Wk3, bk3, Wk4, bk4, Wk5, bk5,
        (float*)d_out, Bn);
}

// round 12
// speedup vs baseline: 1.2443x; 1.2443x over previous
#include <cuda_runtime.h>

// ---------------------------------------------------------------------------
// DFMNET: 2-layer LSTM (B=2048, T=256, I=64, H=128) + 6-layer MLP head.
// R12: R10's proven per-thread economics (8 cols x 8 rows, split-K 2,
// coalesced [chunk][j][cs][float4] weights, depth-1 ring w/ unroll 4), but
// CTA = 8 batch rows / 128 threads so TWO CTAs fit per SM (regs 220*256=56K,
// smem 2*43.3KB). The serial phase chain (GEMM -> act -> GEMM -> act, 4
// barriers/step) of one CTA overlaps the other CTA's GEMM -> fma pipe stays
// fed through activation/barrier windows that R10 paid serially.
// ---------------------------------------------------------------------------

#define T_SEQ    256
#define I_IN     64
#define H_HID    128
#define ROWS     8             // batch rows per CTA
#define NTHREADS 128
#define KROWS    320           // xh rows: [x(64) | h1(128) | h2(128)]
#define GSTR     516           // gate-buffer row stride (floats)
#define BSTR     (ROWS * GSTR) // per-partial-buffer stride (floats)

typedef unsigned long long ull;

// Weights: [chunk][j=0..3][cs=0..63][4 floats] (same as R10). For col-strip
// cs (cols cs*8..cs*8+7), float4 j = (c_{2j}k0, c_{2j}k1, c_{2j+1}k0, c_{2j+1}k1),
// k = 2c, 2c+1. +1 zero-padded chunk so depth-1 prefetch never branches.
__device__ __align__(16) float g_Wt1[(96 + 1) * 1024];    // K=192 -> 96 chunks
__device__ __align__(16) float g_Wt2[(128 + 1) * 1024];   // K=256 -> 128 chunks
__device__ float g_b1[512];
__device__ float g_b2[512];

// ---- packed fp32x2 helpers ----
__device__ __forceinline__ ull fma2(ull a, ull b, ull c) {
    ull d;
    asm("fma.rn.f32x2 %0, %1, %2, %3;" : "=l"(d) : "l"(a), "l"(b), "l"(c));
    return d;
}
__device__ __forceinline__ void unpack2(ull v, float& lo, float& hi) {
    unsigned a, b;
    asm("mov.b64 {%0, %1}, %2;" : "=r"(a), "=r"(b) : "l"(v));
    lo = __uint_as_float(a); hi = __uint_as_float(b);
}
__device__ __forceinline__ ull dup2(float w) {
    ull r; unsigned u = __float_as_uint(w);
    asm("mov.b64 %0, {%1, %1};" : "=l"(r) : "r"(u));
    return r;
}

__device__ __forceinline__ float sigf(float v) {
    return __fdividef(1.f, 1.f + __expf(-v));
}
__device__ __forceinline__ float tanhf_fast(float v) {
    float z = fminf(fmaxf(v, -15.f), 15.f);
    float e = __expf(-2.f * z);
    return __fdividef(1.f - e, 1.f + e);
}

// ---------------------------------------------------------------------------
// Weight repack (identical to R10): [chunk][j][cs][f]
//   e = c*1024 + j*256 + cs*4 + f ;  ci = j*2 + (f>>1), s = f&1
//   g = cs*8 + ci ; k = 2c + s
// ---------------------------------------------------------------------------
__global__ void prep_kernel(const float* __restrict__ Wih1, const float* __restrict__ Whh1,
                            const float* __restrict__ bih1, const float* __restrict__ bhh1,
                            const float* __restrict__ Wih2, const float* __restrict__ Whh2,
                            const float* __restrict__ bih2, const float* __restrict__ bhh2)
{
    int tid = blockIdx.x * blockDim.x + threadIdx.x;
    int stride = gridDim.x * blockDim.x;
    if (tid < 512) {
        g_b1[tid] = bih1[tid] + bhh1[tid];
        g_b2[tid] = bih2[tid] + bhh2[tid];
    }
    for (int e = tid; e < 97 * 1024; e += stride) {
        int c = e >> 10, r = e & 1023;
        int j = r >> 8, cs = (r >> 2) & 63, f = r & 3;
        int ci = j * 2 + (f >> 1), s = f & 1;
        int g = cs * 8 + ci;
        int k = 2 * c + s;
        float w = 0.f;
        if (k < 192) w = (k < 64) ? Wih1[g * 64 + k] : Whh1[g * 128 + (k - 64)];
        g_Wt1[e] = w;
    }
    for (int e = tid; e < 129 * 1024; e += stride) {
        int c = e >> 10, r = e & 1023;
        int j = r >> 8, cs = (r >> 2) & 63, f = r & 3;
        int ci = j * 2 + (f >> 1), s = f & 1;
        int g = cs * 8 + ci;
        int k = 2 * c + s;
        float w = 0.f;
        if (k < 256) w = (k < 128) ? Wih2[g * 128 + k] : Whh2[g * 128 + (k - 128)];
        g_Wt2[e] = w;
    }
}

// ---------------------------------------------------------------------------
// Partial gate GEMM over chunk range [cb, cb+nc):
//   gbuf[8][GSTR] = (bias?) + xh-slice @ Wt-slice for this thread's
//   8 cols (cs*8..cs*8+7) x all 8 rows of the CTA.
// acc[ci][rp] = f32x2 over rows (2rp, 2rp+1), col cs*8+ci.
// Per chunk/thread: 4 coalesced LDG.128 (depth-1 ring, unroll 4 so ptxas
// rotates it), 4 broadcast LDS.128, 16 dup MOVs (alu), 64 FFMA2 (binder).
// ---------------------------------------------------------------------------
__device__ __forceinline__ void gemm_gates(const float* __restrict__ Wt,
                                           const float* __restrict__ bias,
                                           const float* __restrict__ xh,   // [k][8]
                                           float* __restrict__ gbuf,       // [8][GSTR]
                                           int cb, int nc, int cs, bool add_bias)
{
    const int c0 = cs * 8;
    ull acc[8][4];
    if (add_bias) {
#pragma unroll
        for (int ci = 0; ci < 8; ci++) {
            ull b = dup2(bias[c0 + ci]);
#pragma unroll
            for (int rp = 0; rp < 4; rp++) acc[ci][rp] = b;
        }
    } else {
#pragma unroll
        for (int ci = 0; ci < 8; ci++)
#pragma unroll
            for (int rp = 0; rp < 4; rp++) acc[ci][rp] = 0ull;
    }

    // coalesced: lane cs reads float4 at (chunk base) + j*64 float4s + cs
    const float4* Wp = (const float4*)Wt + cb * 256 + cs;
    float4 w0 = Wp[0], w1 = Wp[64], w2 = Wp[128], w3 = Wp[192];
    const ulonglong2* xq = (const ulonglong2*)(xh + cb * 16);   // 2 k-rows = 16 floats

#pragma unroll 4
    for (int c = 0; c < nc; c++) {
        // prefetch next chunk's weights (padded tail: always safe)
        float4 n0 = Wp[256], n1 = Wp[320], n2 = Wp[384], n3 = Wp[448];
        Wp += 256;
        // all 8 rows for k=2c (q0,q1) and k=2c+1 (q2,q3); warp-broadcast
        ulonglong2 q0 = xq[0], q1 = xq[1];
        ulonglong2 q2 = xq[2], q3 = xq[3];
        xq += 4;

        ull t;
        // ci=0
        t = dup2(w0.x);
        acc[0][0] = fma2(t, q0.x, acc[0][0]); acc[0][1] = fma2(t, q0.y, acc[0][1]);
        acc[0][2] = fma2(t, q1.x, acc[0][2]); acc[0][3] = fma2(t, q1.y, acc[0][3]);
        t = dup2(w0.y);
        acc[0][0] = fma2(t, q2.x, acc[0][0]); acc[0][1] = fma2(t, q2.y, acc[0][1]);
        acc[0][2] = fma2(t, q3.x, acc[0][2]); acc[0][3] = fma2(t, q3.y, acc[0][3]);
        // ci=1
        t = dup2(w0.z);
        acc[1][0] = fma2(t, q0.x, acc[1][0]); acc[1][1] = fma2(t, q0.y, acc[1][1]);
        acc[1][2] = fma2(t, q1.x, acc[1][2]); acc[1][3] = fma2(t, q1.y, acc[1][3]);
        t = dup2(w0.w);
        acc[1][0] = fma2(t, q2.x, acc[1][0]); acc[1][1] = fma2(t, q2.y, acc[1][1]);
        acc[1][2] = fma2(t, q3.x, acc[1][2]); acc[1][3] = fma2(t, q3.y, acc[1][3]);
        // ci=2
        t = dup2(w1.x);
        acc[2][0] = fma2(t, q0.x, acc[2][0]); acc[2][1] = fma2(t, q0.y, acc[2][1]);
        acc[2][2] = fma2(t, q1.x, acc[2][2]); acc[2][3] = fma2(t, q1.y, acc[2][3]);
        t = dup2(w1.y);
        acc[2][0] = fma2(t, q2.x, acc[2][0]); acc[2][1] = fma2(t, q2.y, acc[2][1]);
        acc[2][2] = fma2(t, q3.x, acc[2][2]); acc[2][3] = fma2(t, q3.y, acc[2][3]);
        // ci=3
        t = dup2(w1.z);
        acc[3][0] = fma2(t, q0.x, acc[3][0]); acc[3][1] = fma2(t, q0.y, acc[3][1]);
        acc[3][2] = fma2(t, q1.x, acc[3][2]); acc[3][3] = fma2(t, q1.y, acc[3][3]);
        t = dup2(w1.w);
        acc[3][0] = fma2(t, q2.x, acc[3][0]); acc[3][1] = fma2(t, q2.y, acc[3][1]);
        acc[3][2] = fma2(t, q3.x, acc[3][2]); acc[3][3] = fma2(t, q3.y, acc[3][3]);
        // ci=4
        t = dup2(w2.x);
        acc[4][0] = fma2(t, q0.x, acc[4][0]); acc[4][1] = fma2(t, q0.y, acc[4][1]);
        acc[4][2] = fma2(t, q1.x, acc[4][2]); acc[4][3] = fma2(t, q1.y, acc[4][3]);
        t = dup2(w2.y);
        acc[4][0] = fma2(t, q2.x, acc[4][0]); acc[4][1] = fma2(t, q2.y, acc[4][1]);
        acc[4][2] = fma2(t, q3.x, acc[4][2]); acc[4][3] = fma2(t, q3.y, acc[4][3]);
        // ci=5
        t = dup2(w2.z);
        acc[5][0] = fma2(t, q0.x, acc[5][0]); acc[5][1] = fma2(t, q0.y, acc[5][1]);
        acc[5][2] = fma2(t, q1.x, acc[5][2]); acc[5][3] = fma2(t, q1.y, acc[5][3]);
        t = dup2(w2.w);
        acc[5][0] = fma2(t, q2.x, acc[5][0]); acc[5][1] = fma2(t, q2.y, acc[5][1]);
        acc[5][2] = fma2(t, q3.x, acc[5][2]); acc[5][3] = fma2(t, q3.y, acc[5][3]);
        // ci=6
        t = dup2(w3.x);
        acc[6][0] = fma2(t, q0.x, acc[6][0]); acc[6][1] = fma2(t, q0.y, acc[6][1]);
        acc[6][2] = fma2(t, q1.x, acc[6][2]); acc[6][3] = fma2(t, q1.y, acc[6][3]);
        t = dup2(w3.y);
        acc[6][0] = fma2(t, q2.x, acc[6][0]); acc[6][1] = fma2(t, q2.y, acc[6][1]);
        acc[6][2] = fma2(t, q3.x, acc[6][2]); acc[6][3] = fma2(t, q3.y, acc[6][3]);
        // ci=7
        t = dup2(w3.z);
        acc[7][0] = fma2(t, q0.x, acc[7][0]); acc[7][1] = fma2(t, q0.y, acc[7][1]);
        acc[7][2] = fma2(t, q1.x, acc[7][2]); acc[7][3] = fma2(t, q1.y, acc[7][3]);
        t = dup2(w3.w);
        acc[7][0] = fma2(t, q2.x, acc[7][0]); acc[7][1] = fma2(t, q2.y, acc[7][1]);
        acc[7][2] = fma2(t, q3.x, acc[7][2]); acc[7][3] = fma2(t, q3.y, acc[7][3]);

        w0 = n0; w1 = n1; w2 = n2; w3 = n3;
    }

    // write 8 rows x 8 cols: two float4 STS per row
#pragma unroll
    for (int rp = 0; rp < 4; rp++) {
        float la[8], ha[8];
#pragma unroll
        for (int ci = 0; ci < 8; ci++) unpack2(acc[ci][rp], la[ci], ha[ci]);
        int row0 = 2 * rp;
        float* d0 = gbuf + row0 * GSTR + c0;
        float* d1 = d0 + GSTR;
        *(float4*)(d0)     = make_float4(la[0], la[1], la[2], la[3]);
        *(float4*)(d0 + 4) = make_float4(la[4], la[5], la[6], la[7]);
        *(float4*)(d1)     = make_float4(ha[0], ha[1], ha[2], ha[3]);
        *(float4*)(d1 + 4) = make_float4(ha[4], ha[5], ha[6], ha[7]);
    }
}

// Small MLP layer over the CTA's 8 rows (head only; negligible cost)
__device__ __forceinline__ void mlp_layer(const float* __restrict__ vin, int Din,
                                          const float* __restrict__ W, const float* __restrict__ b,
                                          float* __restrict__ vout, int Dout, bool relu, int tid)
{
    for (int e = tid; e < ROWS * Dout; e += NTHREADS) {
        int r = e / Dout, o = e - r * Dout;
        const float* w = W + o * Din;
        const float* vi = vin + r * Din;
        float s = b[o];
        for (int i = 0; i < Din; i += 4) {
            s += w[i] * vi[i] + w[i + 1] * vi[i + 1] + w[i + 2] * vi[i + 2] + w[i + 3] * vi[i + 3];
        }
        vout[e] = relu ? fmaxf(s, 0.f) : s;
    }
    __syncthreads();
}

// ---------------------------------------------------------------------------
__global__ void __launch_bounds__(NTHREADS, 2)
dfmnet_main(const float* __restrict__ x,
            const float* __restrict__ Wk0, const float* __restrict__ bk0,
            const float* __restrict__ Wk1, const float* __restrict__ bk1,
            const float* __restrict__ Wk2, const float* __restrict__ bk2,
            const float* __restrict__ Wk3, const float* __restrict__ bk3,
            const float* __restrict__ Wk4, const float* __restrict__ bk4,
            const float* __restrict__ Wk5, const float* __restrict__ bk5,
            float* __restrict__ out, int Bn)
{
    extern __shared__ float sm[];
    float* xh    = sm;                    // [KROWS][8]
    float* gates = sm + KROWS * ROWS;     // 2 partial buffers [8][GSTR] each

    const int tid = threadIdx.x;
    const int kg  = tid >> 6;             // k-group 0/1 (2 warps each)
    const int cs  = tid & 63;             // col-strip: cols cs*8..cs*8+7
    const int b0  = blockIdx.x * ROWS;

    for (int e = tid; e < KROWS * ROWS; e += NTHREADS) xh[e] = 0.f;
    float c1r[8], c2r[8];
#pragma unroll
    for (int p = 0; p < 8; p++) { c1r[p] = 0.f; c2r[p] = 0.f; }
    __syncthreads();

    const float* xbase = x + (size_t)b0 * T_SEQ * I_IN;
    float* mybuf = gates + kg * BSTR;

    for (int t = 0; t < T_SEQ; t++) {
        // load x_t (8 rows x 64) transposed into xh rows [0,64)
#pragma unroll
        for (int q = 0; q < 4; q++) {
            int e = tid + q * NTHREADS;            // 0..511
            int r = e >> 6, k = e & 63;
            xh[k * ROWS + r] = xbase[(size_t)r * (T_SEQ * I_IN) + t * I_IN + k];
        }
        __syncthreads();

        // layer 1: K=192 -> 96 chunks, 48 per k-group
        gemm_gates(g_Wt1, g_b1, xh, mybuf, kg * 48, 48, cs, kg == 0);
        __syncthreads();

        // layer 1 activation: h1 -> xh rows [64,192); sum 2 partials
#pragma unroll
        for (int p = 0; p < 8; p++) {
            int idx = tid + p * NTHREADS;          // 0..1023
            int j = idx >> 3, r = idx & 7;
            const float* gb = gates + r * GSTR + j;
            float pi = gb[0]   + gb[BSTR];
            float pf = gb[128] + gb[BSTR + 128];
            float pg = gb[256] + gb[BSTR + 256];
            float po = gb[384] + gb[BSTR + 384];
            float iv = sigf(pi);
            float fv = sigf(pf);
            float gv = tanhf_fast(pg);
            float ov = sigf(po);
            float c = fv * c1r[p] + iv * gv;
            c1r[p] = c;
            xh[(64 + j) * ROWS + r] = ov * tanhf_fast(c);
        }
        __syncthreads();

        // layer 2: K=256 -> 128 chunks, 64 per k-group; xh rows [64,320)
        gemm_gates(g_Wt2, g_b2, xh + 64 * ROWS, mybuf, kg * 64, 64, cs, kg == 0);
        __syncthreads();

        // layer 2 activation: h2 -> xh rows [192,320)
#pragma unroll
        for (int p = 0; p < 8; p++) {
            int idx = tid + p * NTHREADS;
            int j = idx >> 3, r = idx & 7;
            const float* gb = gates + r * GSTR + j;
            float pi = gb[0]   + gb[BSTR];
            float pf = gb[128] + gb[BSTR + 128];
            float pg = gb[256] + gb[BSTR + 256];
            float po = gb[384] + gb[BSTR + 384];
            float iv = sigf(pi);
            float fv = sigf(pf);
            float gv = tanhf_fast(pg);
            float ov = sigf(po);
            float c = fv * c2r[p] + iv * gv;
            c2r[p] = c;
            xh[(192 + j) * ROWS + r] = ov * tanhf_fast(c);
        }
        // next iter's x-load writes disjoint smem; its __syncthreads orders
        // these h2 writes (and this phase's gates reads) before reuse.
    }
    __syncthreads();

    // ---- outputs: tuple (y, h2, r) flattened ----
    float* out_y  = out;                              // [Bn][64]
    float* out_h2 = out + (size_t)Bn * 64;            // [Bn][128]
    float* out_r  = out + (size_t)Bn * 192;           // [Bn][192]

    float* va = gates;              // [8][192]
    float* vb = gates + ROWS * 192; // [8][128]
    float* vc = vb + ROWS * 128;    // [8][128]
    for (int e = tid; e < ROWS * 192; e += NTHREADS) {
        int r = e / 192, j = e - r * 192;
        float v = (j < 128) ? xh[(192 + j) * ROWS + r] : xh[(j - 128) * ROWS + r];
        va[e] = v;
        out_r[(size_t)(b0 + r) * 192 + j] = v;
        if (j < 128) out_h2[(size_t)(b0 + r) * 128 + j] = v;
    }
    __syncthreads();

    mlp_layer(va, 192, Wk0, bk0, vb, 128, true, tid);
    mlp_layer(vb, 128, Wk1, bk1, vc, 128, true, tid);
    mlp_layer(vc, 128, Wk2, bk2, vb, 128, true, tid);
    mlp_layer(vb, 128, Wk3, bk3, vc, 128, true, tid);
    mlp_layer(vc, 128, Wk4, bk4, vb, 128, true, tid);

    for (int e = tid; e < ROWS * 64; e += NTHREADS) {
        int r = e >> 6, o = e & 63;
        const float* w = Wk5 + o * 128;
        const float* vi = vb + r * 128;
        float s = bk5[o];
        for (int i = 0; i < 128; i += 4) {
            s += w[i] * vi[i] + w[i + 1] * vi[i + 1] + w[i + 2] * vi[i + 2] + w[i + 3] * vi[i + 3];
        }
        out_y[(size_t)(b0 + r) * 64 + o] = s;
    }
}

// ---------------------------------------------------------------------------
extern "C" void kernel_launch(void* const* d_in, const int* in_sizes, int n_in,
                              void* d_out, int out_size)
{
    const float* x    = (const float*)d_in[0];
    const float* Wih1 = (const float*)d_in[1];
    const float* Whh1 = (const float*)d_in[2];
    const float* bih1 = (const float*)d_in[3];
    const float* bhh1 = (const float*)d_in[4];
    const float* Wih2 = (const float*)d_in[5];
    const float* Whh2 = (const float*)d_in[6];
    const float* bih2 = (const float*)d_in[7];
    const float* bhh2 = (const float*)d_in[8];
    const float* Wk0 = (const float*)d_in[9];   const float* bk0 = (const float*)d_in[10];
    const float* Wk1 = (const float*)d_in[11];  const float* bk1 = (const float*)d_in[12];
    const float* Wk2 = (const float*)d_in[13];  const float* bk2 = (const float*)d_in[14];
    const float* Wk3 = (const float*)d_in[15];  const float* bk3 = (const float*)d_in[16];
    const float* Wk4 = (const float*)d_in[17];  const float* bk4 = (const float*)d_in[18];
    const float* Wk5 = (const float*)d_in[19];  const float* bk5 = (const float*)d_in[20];

    int Bn = in_sizes[0] / (T_SEQ * I_IN);
    int smem_bytes = (KROWS * ROWS + 2 * ROWS * GSTR) * (int)sizeof(float);  // 43264 B

    cudaFuncSetAttribute(dfmnet_main, cudaFuncAttributeMaxDynamicSharedMemorySize, smem_bytes);

    prep_kernel<<<208, 256>>>(Wih1, Whh1, bih1, bhh1, Wih2, Whh2, bih2, bhh2);
    dfmnet_main<<<Bn / ROWS, NTHREADS, smem_bytes>>>(
        x, Wk0, bk0, Wk1, bk1, Wk2, bk2, Wk3, bk3, Wk4, bk4, Wk5, bk5,
        (float*)d_out, Bn);
}

// round 13
// speedup vs baseline: 1.2636x; 1.0155x over previous
#include <cuda_runtime.h>

// ---------------------------------------------------------------------------
// DFMNET: 2-layer LSTM (B=2048, T=256, I=64, H=128) + 6-layer MLP head.
// R13: two INDEPENDENT 8-row workers inside one 256-thread CTA, each using a
// private named barrier (bar.sync 1,128 / bar.sync 2,128). Rows are
// independent, so the groups never cross-sync: each SMSP carries one warp of
// each group, and one group's GEMM FFMA2 stream fills the other group's
// activation/MUFU/barrier windows. Grid = 128 CTAs = 1/SM (R12 proved the
// overlap but lost it to 256-CTA grid imbalance on 148 SMs).
// Per-group economics identical to R12: 8 cols x 8 rows/thread, split-K 2,
// coalesced [chunk][j][cs][float4] weights, depth-1 ring @ unroll 4.
// ---------------------------------------------------------------------------

#define T_SEQ    256
#define I_IN     64
#define H_HID    128
#define GROWS    8             // batch rows per group
#define NTHREADS 256
#define GT       128           // threads per group
#define KROWS    320           // xh rows: [x(64) | h1(128) | h2(128)]
#define GSTR     516           // gate-buffer row stride (floats)
#define BSTR     (GROWS * GSTR)
#define GRP_F    (KROWS * GROWS + 2 * BSTR)   // floats of smem per group: 10816

typedef unsigned long long ull;

// Weights: [chunk][j=0..3][cs=0..63][4 floats]. For col-strip cs (cols
// cs*8..cs*8+7), float4 j = (c_{2j}k0, c_{2j}k1, c_{2j+1}k0, c_{2j+1}k1),
// k = 2c, 2c+1. +1 zero-padded chunk so depth-1 prefetch never branches.
__device__ __align__(16) float g_Wt1[(96 + 1) * 1024];    // K=192 -> 96 chunks
__device__ __align__(16) float g_Wt2[(128 + 1) * 1024];   // K=256 -> 128 chunks
__device__ float g_b1[512];
__device__ float g_b2[512];

// group-private barrier: ids 1 and 2, 128 threads each
#define GBAR(bid) asm volatile("bar.sync %0, 128;" :: "r"(bid) : "memory")

// ---- packed fp32x2 helpers ----
__device__ __forceinline__ ull fma2(ull a, ull b, ull c) {
    ull d;
    asm("fma.rn.f32x2 %0, %1, %2, %3;" : "=l"(d) : "l"(a), "l"(b), "l"(c));
    return d;
}
__device__ __forceinline__ void unpack2(ull v, float& lo, float& hi) {
    unsigned a, b;
    asm("mov.b64 {%0, %1}, %2;" : "=r"(a), "=r"(b) : "l"(v));
    lo = __uint_as_float(a); hi = __uint_as_float(b);
}
__device__ __forceinline__ ull dup2(float w) {
    ull r; unsigned u = __float_as_uint(w);
    asm("mov.b64 %0, {%1, %1};" : "=l"(r) : "r"(u));
    return r;
}

__device__ __forceinline__ float sigf(float v) {
    return __fdividef(1.f, 1.f + __expf(-v));
}
__device__ __forceinline__ float tanhf_fast(float v) {
    float z = fminf(fmaxf(v, -15.f), 15.f);
    float e = __expf(-2.f * z);
    return __fdividef(1.f - e, 1.f + e);
}

// ---------------------------------------------------------------------------
// Weight repack (identical layout to R10/R12): [chunk][j][cs][f]
// ---------------------------------------------------------------------------
__global__ void prep_kernel(const float* __restrict__ Wih1, const float* __restrict__ Whh1,
                            const float* __restrict__ bih1, const float* __restrict__ bhh1,
                            const float* __restrict__ Wih2, const float* __restrict__ Whh2,
                            const float* __restrict__ bih2, const float* __restrict__ bhh2)
{
    int tid = blockIdx.x * blockDim.x + threadIdx.x;
    int stride = gridDim.x * blockDim.x;
    if (tid < 512) {
        g_b1[tid] = bih1[tid] + bhh1[tid];
        g_b2[tid] = bih2[tid] + bhh2[tid];
    }
    for (int e = tid; e < 97 * 1024; e += stride) {
        int c = e >> 10, r = e & 1023;
        int j = r >> 8, cs = (r >> 2) & 63, f = r & 3;
        int ci = j * 2 + (f >> 1), s = f & 1;
        int g = cs * 8 + ci;
        int k = 2 * c + s;
        float w = 0.f;
        if (k < 192) w = (k < 64) ? Wih1[g * 64 + k] : Whh1[g * 128 + (k - 64)];
        g_Wt1[e] = w;
    }
    for (int e = tid; e < 129 * 1024; e += stride) {
        int c = e >> 10, r = e & 1023;
        int j = r >> 8, cs = (r >> 2) & 63, f = r & 3;
        int ci = j * 2 + (f >> 1), s = f & 1;
        int g = cs * 8 + ci;
        int k = 2 * c + s;
        float w = 0.f;
        if (k < 256) w = (k < 128) ? Wih2[g * 128 + k] : Whh2[g * 128 + (k - 128)];
        g_Wt2[e] = w;
    }
}

// ---------------------------------------------------------------------------
// Partial gate GEMM over chunk range [cb, cb+nc) for one group's 8 rows:
//   gbuf[8][GSTR] = (bias?) + xh-slice @ Wt-slice for this thread's
//   8 cols (cs*8..cs*8+7). acc[ci][rp] = f32x2 rows (2rp, 2rp+1).
// Per chunk/thread: 4 coalesced LDG.128 (depth-1 ring, unroll 4 for reg
// rotation), 4 broadcast LDS.128, 16 dup MOVs (alu), 64 FFMA2 (binder).
// ---------------------------------------------------------------------------
__device__ __forceinline__ void gemm_gates(const float* __restrict__ Wt,
                                           const float* __restrict__ bias,
                                           const float* __restrict__ xh,   // [k][8]
                                           float* __restrict__ gbuf,       // [8][GSTR]
                                           int cb, int nc, int cs, bool add_bias)
{
    const int c0 = cs * 8;
    ull acc[8][4];
    if (add_bias) {
#pragma unroll
        for (int ci = 0; ci < 8; ci++) {
            ull b = dup2(bias[c0 + ci]);
#pragma unroll
            for (int rp = 0; rp < 4; rp++) acc[ci][rp] = b;
        }
    } else {
#pragma unroll
        for (int ci = 0; ci < 8; ci++)
#pragma unroll
            for (int rp = 0; rp < 4; rp++) acc[ci][rp] = 0ull;
    }

    const float4* Wp = (const float4*)Wt + cb * 256 + cs;
    float4 w0 = Wp[0], w1 = Wp[64], w2 = Wp[128], w3 = Wp[192];
    const ulonglong2* xq = (const ulonglong2*)(xh + cb * 16);   // 2 k-rows = 16 floats

#pragma unroll 4
    for (int c = 0; c < nc; c++) {
        float4 n0 = Wp[256], n1 = Wp[320], n2 = Wp[384], n3 = Wp[448];
        Wp += 256;
        ulonglong2 q0 = xq[0], q1 = xq[1];   // k = 2c, rows 0..7
        ulonglong2 q2 = xq[2], q3 = xq[3];   // k = 2c+1
        xq += 4;

        ull t;
        t = dup2(w0.x);
        acc[0][0] = fma2(t, q0.x, acc[0][0]); acc[0][1] = fma2(t, q0.y, acc[0][1]);
        acc[0][2] = fma2(t, q1.x, acc[0][2]); acc[0][3] = fma2(t, q1.y, acc[0][3]);
        t = dup2(w0.y);
        acc[0][0] = fma2(t, q2.x, acc[0][0]); acc[0][1] = fma2(t, q2.y, acc[0][1]);
        acc[0][2] = fma2(t, q3.x, acc[0][2]); acc[0][3] = fma2(t, q3.y, acc[0][3]);
        t = dup2(w0.z);
        acc[1][0] = fma2(t, q0.x, acc[1][0]); acc[1][1] = fma2(t, q0.y, acc[1][1]);
        acc[1][2] = fma2(t, q1.x, acc[1][2]); acc[1][3] = fma2(t, q1.y, acc[1][3]);
        t = dup2(w0.w);
        acc[1][0] = fma2(t, q2.x, acc[1][0]); acc[1][1] = fma2(t, q2.y, acc[1][1]);
        acc[1][2] = fma2(t, q3.x, acc[1][2]); acc[1][3] = fma2(t, q3.y, acc[1][3]);
        t = dup2(w1.x);
        acc[2][0] = fma2(t, q0.x, acc[2][0]); acc[2][1] = fma2(t, q0.y, acc[2][1]);
        acc[2][2] = fma2(t, q1.x, acc[2][2]); acc[2][3] = fma2(t, q1.y, acc[2][3]);
        t = dup2(w1.y);
        acc[2][0] = fma2(t, q2.x, acc[2][0]); acc[2][1] = fma2(t, q2.y, acc[2][1]);
        acc[2][2] = fma2(t, q3.x, acc[2][2]); acc[2][3] = fma2(t, q3.y, acc[2][3]);
        t = dup2(w1.z);
        acc[3][0] = fma2(t, q0.x, acc[3][0]); acc[3][1] = fma2(t, q0.y, acc[3][1]);
        acc[3][2] = fma2(t, q1.x, acc[3][2]); acc[3][3] = fma2(t, q1.y, acc[3][3]);
        t = dup2(w1.w);
        acc[3][0] = fma2(t, q2.x, acc[3][0]); acc[3][1] = fma2(t, q2.y, acc[3][1]);
        acc[3][2] = fma2(t, q3.x, acc[3][2]); acc[3][3] = fma2(t, q3.y, acc[3][3]);
        t = dup2(w2.x);
        acc[4][0] = fma2(t, q0.x, acc[4][0]); acc[4][1] = fma2(t, q0.y, acc[4][1]);
        acc[4][2] = fma2(t, q1.x, acc[4][2]); acc[4][3] = fma2(t, q1.y, acc[4][3]);
        t = dup2(w2.y);
        acc[4][0] = fma2(t, q2.x, acc[4][0]); acc[4][1] = fma2(t, q2.y, acc[4][1]);
        acc[4][2] = fma2(t, q3.x, acc[4][2]); acc[4][3] = fma2(t, q3.y, acc[4][3]);
        t = dup2(w2.z);
        acc[5][0] = fma2(t, q0.x, acc[5][0]); acc[5][1] = fma2(t, q0.y, acc[5][1]);
        acc[5][2] = fma2(t, q1.x, acc[5][2]); acc[5][3] = fma2(t, q1.y, acc[5][3]);
        t = dup2(w2.w);
        acc[5][0] = fma2(t, q2.x, acc[5][0]); acc[5][1] = fma2(t, q2.y, acc[5][1]);
        acc[5][2] = fma2(t, q3.x, acc[5][2]); acc[5][3] = fma2(t, q3.y, acc[5][3]);
        t = dup2(w3.x);
        acc[6][0] = fma2(t, q0.x, acc[6][0]); acc[6][1] = fma2(t, q0.y, acc[6][1]);
        acc[6][2] = fma2(t, q1.x, acc[6][2]); acc[6][3] = fma2(t, q1.y, acc[6][3]);
        t = dup2(w3.y);
        acc[6][0] = fma2(t, q2.x, acc[6][0]); acc[6][1] = fma2(t, q2.y, acc[6][1]);
        acc[6][2] = fma2(t, q3.x, acc[6][2]); acc[6][3] = fma2(t, q3.y, acc[6][3]);
        t = dup2(w3.z);
        acc[7][0] = fma2(t, q0.x, acc[7][0]); acc[7][1] = fma2(t, q0.y, acc[7][1]);
        acc[7][2] = fma2(t, q1.x, acc[7][2]); acc[7][3] = fma2(t, q1.y, acc[7][3]);
        t = dup2(w3.w);
        acc[7][0] = fma2(t, q2.x, acc[7][0]); acc[7][1] = fma2(t, q2.y, acc[7][1]);
        acc[7][2] = fma2(t, q3.x, acc[7][2]); acc[7][3] = fma2(t, q3.y, acc[7][3]);

        w0 = n0; w1 = n1; w2 = n2; w3 = n3;
    }

#pragma unroll
    for (int rp = 0; rp < 4; rp++) {
        float la[8], ha[8];
#pragma unroll
        for (int ci = 0; ci < 8; ci++) unpack2(acc[ci][rp], la[ci], ha[ci]);
        int row0 = 2 * rp;
        float* d0 = gbuf + row0 * GSTR + c0;
        float* d1 = d0 + GSTR;
        *(float4*)(d0)     = make_float4(la[0], la[1], la[2], la[3]);
        *(float4*)(d0 + 4) = make_float4(la[4], la[5], la[6], la[7]);
        *(float4*)(d1)     = make_float4(ha[0], ha[1], ha[2], ha[3]);
        *(float4*)(d1 + 4) = make_float4(ha[4], ha[5], ha[6], ha[7]);
    }
}

// Small MLP layer over one group's 8 rows (head only; negligible cost)
__device__ __forceinline__ void mlp_layer(const float* __restrict__ vin, int Din,
                                          const float* __restrict__ W, const float* __restrict__ b,
                                          float* __restrict__ vout, int Dout,
                                          bool relu, int gtid, int bid)
{
    for (int e = gtid; e < GROWS * Dout; e += GT) {
        int r = e / Dout, o = e - r * Dout;
        const float* w = W + o * Din;
        const float* vi = vin + r * Din;
        float s = b[o];
        for (int i = 0; i < Din; i += 4) {
            s += w[i] * vi[i] + w[i + 1] * vi[i + 1] + w[i + 2] * vi[i + 2] + w[i + 3] * vi[i + 3];
        }
        vout[e] = relu ? fmaxf(s, 0.f) : s;
    }
    GBAR(bid);
}

// ---------------------------------------------------------------------------
__global__ void __launch_bounds__(NTHREADS, 1)
dfmnet_main(const float* __restrict__ x,
            const float* __restrict__ Wk0, const float* __restrict__ bk0,
            const float* __restrict__ Wk1, const float* __restrict__ bk1,
            const float* __restrict__ Wk2, const float* __restrict__ bk2,
            const float* __restrict__ Wk3, const float* __restrict__ bk3,
            const float* __restrict__ Wk4, const float* __restrict__ bk4,
            const float* __restrict__ Wk5, const float* __restrict__ bk5,
            float* __restrict__ out, int Bn)
{
    extern __shared__ float sm[];

    const int tid  = threadIdx.x;
    const int grp  = tid >> 7;            // group 0/1 (warps 0-3 / 4-7)
    const int gtid = tid & 127;           // thread id within group
    const int bid  = grp + 1;             // named barrier id (1 or 2)
    const int kg   = gtid >> 6;           // k-group 0/1 within the group
    const int cs   = gtid & 63;           // col-strip: cols cs*8..cs*8+7
    const int b0   = blockIdx.x * 16 + grp * GROWS;   // this group's rows

    float* xh    = sm + grp * GRP_F;              // [KROWS][8]
    float* gates = xh + KROWS * GROWS;            // 2 partial buffers [8][GSTR]
    float* mybuf = gates + kg * BSTR;

    for (int e = gtid; e < GRP_F; e += GT) xh[e] = 0.f;
    float c1r[8], c2r[8];
#pragma unroll
    for (int p = 0; p < 8; p++) { c1r[p] = 0.f; c2r[p] = 0.f; }
    GBAR(bid);

    const float* xbase = x + (size_t)b0 * T_SEQ * I_IN;

    for (int t = 0; t < T_SEQ; t++) {
        // load x_t (8 rows x 64) transposed into xh rows [0,64)
#pragma unroll
        for (int q = 0; q < 4; q++) {
            int e = gtid + q * GT;                 // 0..511
            int r = e >> 6, k = e & 63;
            xh[k * GROWS + r] = xbase[(size_t)r * (T_SEQ * I_IN) + t * I_IN + k];
        }
        GBAR(bid);

        // layer 1: K=192 -> 96 chunks, 48 per k-group
        gemm_gates(g_Wt1, g_b1, xh, mybuf, kg * 48, 48, cs, kg == 0);
        GBAR(bid);

        // layer 1 activation: h1 -> xh rows [64,192); sum 2 partials
#pragma unroll
        for (int p = 0; p < 8; p++) {
            int idx = gtid + p * GT;               // 0..1023
            int j = idx >> 3, r = idx & 7;
            const float* gb = gates + r * GSTR + j;
            float pi = gb[0]   + gb[BSTR];
            float pf = gb[128] + gb[BSTR + 128];
            float pg = gb[256] + gb[BSTR + 256];
            float po = gb[384] + gb[BSTR + 384];
            float iv = sigf(pi);
            float fv = sigf(pf);
            float gv = tanhf_fast(pg);
            float ov = sigf(po);
            float c = fv * c1r[p] + iv * gv;
            c1r[p] = c;
            xh[(64 + j) * GROWS + r] = ov * tanhf_fast(c);
        }
        GBAR(bid);

        // layer 2: K=256 -> 128 chunks, 64 per k-group; xh rows [64,320)
        gemm_gates(g_Wt2, g_b2, xh + 64 * GROWS, mybuf, kg * 64, 64, cs, kg == 0);
        GBAR(bid);

        // layer 2 activation: h2 -> xh rows [192,320)
#pragma unroll
        for (int p = 0; p < 8; p++) {
            int idx = gtid + p * GT;
            int j = idx >> 3, r = idx & 7;
            const float* gb = gates + r * GSTR + j;
            float pi = gb[0]   + gb[BSTR];
            float pf = gb[128] + gb[BSTR + 128];
            float pg = gb[256] + gb[BSTR + 256];
            float po = gb[384] + gb[BSTR + 384];
            float iv = sigf(pi);
            float fv = sigf(pf);
            float gv = tanhf_fast(pg);
            float ov = sigf(po);
            float c = fv * c2r[p] + iv * gv;
            c2r[p] = c;
            xh[(192 + j) * GROWS + r] = ov * tanhf_fast(c);
        }
        // next iter's x-load writes disjoint smem; its GBAR orders these h2
        // writes (and this phase's gates reads) before reuse.
    }
    GBAR(bid);

    // ---- outputs: tuple (y, h2, r) flattened ----
    float* out_y  = out;                              // [Bn][64]
    float* out_h2 = out + (size_t)Bn * 64;            // [Bn][128]
    float* out_r  = out + (size_t)Bn * 192;           // [Bn][192]

    float* va = gates;               // [8][192]
    float* vb = gates + GROWS * 192; // [8][128]
    float* vc = vb + GROWS * 128;    // [8][128]
    for (int e = gtid; e < GROWS * 192; e += GT) {
        int r = e / 192, j = e - r * 192;
        float v = (j < 128) ? xh[(192 + j) * GROWS + r] : xh[(j - 128) * GROWS + r];
        va[e] = v;
        out_r[(size_t)(b0 + r) * 192 + j] = v;
        if (j < 128) out_h2[(size_t)(b0 + r) * 128 + j] = v;
    }
    GBAR(bid);

    mlp_layer(va, 192, Wk0, bk0, vb, 128, true, gtid, bid);
    mlp_layer(vb, 128, Wk1, bk1, vc, 128, true, gtid, bid);
    mlp_layer(vc, 128, Wk2, bk2, vb, 128, true, gtid, bid);
    mlp_layer(vb, 128, Wk3, bk3, vc, 128, true, gtid, bid);
    mlp_layer(vc, 128, Wk4, bk4, vb, 128, true, gtid, bid);

    for (int e = gtid; e < GROWS * 64; e += GT) {
        int r = e >> 6, o = e & 63;
        const float* w = Wk5 + o * 128;
        const float* vi = vb + r * 128;
        float s = bk5[o];
        for (int i = 0; i < 128; i += 4) {
            s += w[i] * vi[i] + w[i + 1] * vi[i + 1] + w[i + 2] * vi[i + 2] + w[i + 3] * vi[i + 3];
        }
        out_y[(size_t)(b0 + r) * 64 + o] = s;
    }
}

// ---------------------------------------------------------------------------
extern "C" void kernel_launch(void* const* d_in, const int* in_sizes, int n_in,
                              void* d_out, int out_size)
{
    const float* x    = (const float*)d_in[0];
    const float* Wih1 = (const float*)d_in[1];
    const float* Whh1 = (const float*)d_in[2];
    const float* bih1 = (const float*)d_in[3];
    const float* bhh1 = (const float*)d_in[4];
    const float* Wih2 = (const float*)d_in[5];
    const float* Whh2 = (const float*)d_in[6];
    const float* bih2 = (const float*)d_in[7];
    const float* bhh2 = (const float*)d_in[8];
    const float* Wk0 = (const float*)d_in[9];   const float* bk0 = (const float*)d_in[10];
    const float* Wk1 = (const float*)d_in[11];  const float* bk1 = (const float*)d_in[12];
    const float* Wk2 = (const float*)d_in[13];  const float* bk2 = (const float*)d_in[14];
    const float* Wk3 = (const float*)d_in[15];  const float* bk3 = (const float*)d_in[16];
    const float* Wk4 = (const float*)d_in[17];  const float* bk4 = (const float*)d_in[18];
    const float* Wk5 = (const float*)d_in[19];  const float* bk5 = (const float*)d_in[20];

    int Bn = in_sizes[0] / (T_SEQ * I_IN);
    int smem_bytes = 2 * GRP_F * (int)sizeof(float);   // 86528 B

    cudaFuncSetAttribute(dfmnet_main, cudaFuncAttributeMaxDynamicSharedMemorySize, smem_bytes);

    prep_kernel<<<208, 256>>>(Wih1, Whh1, bih1, bhh1, Wih2, Whh2, bih2, bhh2);
    dfmnet_main<<<Bn / 16, NTHREADS, smem_bytes>>>(
        x, Wk0, bk0, Wk1, bk1, Wk2, bk2, Wk3, bk3, Wk4, bk4, Wk5, bk5,
        (float*)d_out, Bn);
}

// round 14
// speedup vs baseline: 1.3134x; 1.0394x over previous
#include <cuda_runtime.h>

// ---------------------------------------------------------------------------
// DFMNET: 2-layer LSTM (B=2048, T=256, I=64, H=128) + 6-layer MLP head.
// R14 = R10 (best: 8 cols x 8 rows/thread, 256 thr, split-K 2, coalesced
// [chunk][j][cs][float4] weights, depth-1 ring @ unroll 4) plus three
// latency removals:
//  1. q (activation) registers double-buffered like the weights -> no
//     per-chunk LDS.29 stall in the FFMA chain.
//  2. x_{t+1} prefetched into registers during the layer-2 GEMM.
//  3. x smem store merged into the act-2 phase -> one fewer serial phase
//     per timestep (4 phases / 4 barriers).
// ---------------------------------------------------------------------------

#define T_SEQ    256
#define I_IN     64
#define H_HID    128
#define ROWS     16            // batch rows per CTA
#define NTHREADS 256
#define KROWS    320           // xh rows: [x(64) | h1(128) | h2(128)]
#define GSTR     516           // gate-buffer row stride (floats)
#define BSTR     (ROWS * GSTR) // per-partial-buffer stride (floats)

typedef unsigned long long ull;

// Weights: [chunk][j=0..3][cs=0..63][4 floats]; float4 j of strip cs =
// (c_{2j}k0, c_{2j}k1, c_{2j+1}k0, c_{2j+1}k1) for cols cs*8..cs*8+7,
// k = 2c, 2c+1. +1 zero-padded chunk so depth-1 prefetch never branches.
__device__ __align__(16) float g_Wt1[(96 + 1) * 1024];    // K=192 -> 96 chunks
__device__ __align__(16) float g_Wt2[(128 + 1) * 1024];   // K=256 -> 128 chunks
__device__ float g_b1[512];
__device__ float g_b2[512];

// ---- packed fp32x2 helpers ----
__device__ __forceinline__ ull fma2(ull a, ull b, ull c) {
    ull d;
    asm("fma.rn.f32x2 %0, %1, %2, %3;" : "=l"(d) : "l"(a), "l"(b), "l"(c));
    return d;
}
__device__ __forceinline__ void unpack2(ull v, float& lo, float& hi) {
    unsigned a, b;
    asm("mov.b64 {%0, %1}, %2;" : "=r"(a), "=r"(b) : "l"(v));
    lo = __uint_as_float(a); hi = __uint_as_float(b);
}
__device__ __forceinline__ ull dup2(float w) {
    ull r; unsigned u = __float_as_uint(w);
    asm("mov.b64 %0, {%1, %1};" : "=l"(r) : "r"(u));
    return r;
}

__device__ __forceinline__ float sigf(float v) {
    return __fdividef(1.f, 1.f + __expf(-v));
}
__device__ __forceinline__ float tanhf_fast(float v) {
    float z = fminf(fmaxf(v, -15.f), 15.f);
    float e = __expf(-2.f * z);
    return __fdividef(1.f - e, 1.f + e);
}

// ---------------------------------------------------------------------------
// Weight repack (identical to R10): [chunk][j][cs][f]
//   e = c*1024 + j*256 + cs*4 + f ;  ci = j*2 + (f>>1), s = f&1
//   g = cs*8 + ci ; k = 2c + s
// ---------------------------------------------------------------------------
__global__ void prep_kernel(const float* __restrict__ Wih1, const float* __restrict__ Whh1,
                            const float* __restrict__ bih1, const float* __restrict__ bhh1,
                            const float* __restrict__ Wih2, const float* __restrict__ Whh2,
                            const float* __restrict__ bih2, const float* __restrict__ bhh2)
{
    int tid = blockIdx.x * blockDim.x + threadIdx.x;
    int stride = gridDim.x * blockDim.x;
    if (tid < 512) {
        g_b1[tid] = bih1[tid] + bhh1[tid];
        g_b2[tid] = bih2[tid] + bhh2[tid];
    }
    for (int e = tid; e < 97 * 1024; e += stride) {
        int c = e >> 10, r = e & 1023;
        int j = r >> 8, cs = (r >> 2) & 63, f = r & 3;
        int ci = j * 2 + (f >> 1), s = f & 1;
        int g = cs * 8 + ci;
        int k = 2 * c + s;
        float w = 0.f;
        if (k < 192) w = (k < 64) ? Wih1[g * 64 + k] : Whh1[g * 128 + (k - 64)];
        g_Wt1[e] = w;
    }
    for (int e = tid; e < 129 * 1024; e += stride) {
        int c = e >> 10, r = e & 1023;
        int j = r >> 8, cs = (r >> 2) & 63, f = r & 3;
        int ci = j * 2 + (f >> 1), s = f & 1;
        int g = cs * 8 + ci;
        int k = 2 * c + s;
        float w = 0.f;
        if (k < 256) w = (k < 128) ? Wih2[g * 128 + k] : Whh2[g * 128 + (k - 128)];
        g_Wt2[e] = w;
    }
}

// ---------------------------------------------------------------------------
// Partial gate GEMM over chunk range [cb, cb+nc):
//   gbuf[16][GSTR] = (bias?) + xh-slice @ Wt-slice for this thread's
//   8 cols (cs*8..cs*8+7) x 8 rows (rg*8..rg*8+7).
// BOTH weights and activations are depth-1 double-buffered: the prefetches
// read one chunk past the range, which lands in valid smem (xh/gates) and is
// never consumed. Per chunk/thread: 4 coalesced LDG.128 + 4 broadcast
// LDS.128 (both prefetched), 16 dup MOVs (alu), 64 FFMA2 (the binder).
// ---------------------------------------------------------------------------
__device__ __forceinline__ void gemm_gates(const float* __restrict__ Wt,
                                           const float* __restrict__ bias,
                                           const float* __restrict__ xh,   // [k][16]
                                           float* __restrict__ gbuf,       // [16][GSTR]
                                           int cb, int nc, int rg, int cs, bool add_bias)
{
    const int c0 = cs * 8;
    ull acc[8][4];
    if (add_bias) {
#pragma unroll
        for (int ci = 0; ci < 8; ci++) {
            ull b = dup2(bias[c0 + ci]);
#pragma unroll
            for (int rp = 0; rp < 4; rp++) acc[ci][rp] = b;
        }
    } else {
#pragma unroll
        for (int ci = 0; ci < 8; ci++)
#pragma unroll
            for (int rp = 0; rp < 4; rp++) acc[ci][rp] = 0ull;
    }

    const float4* Wp = (const float4*)Wt + cb * 256 + cs;
    float4 w0 = Wp[0], w1 = Wp[64], w2 = Wp[128], w3 = Wp[192];
    const ulonglong2* xq = (const ulonglong2*)(xh + cb * 32 + rg * 8);
    ulonglong2 q0 = xq[0], q1 = xq[1];   // k = 2cb, rows rg*8..rg*8+7
    ulonglong2 q2 = xq[4], q3 = xq[5];   // k = 2cb+1

#pragma unroll 4
    for (int c = 0; c < nc; c++) {
        // prefetch next chunk (padded tail / valid-smem overread: safe)
        float4 n0 = Wp[256], n1 = Wp[320], n2 = Wp[384], n3 = Wp[448];
        Wp += 256;
        ulonglong2 p0 = xq[8],  p1 = xq[9];
        ulonglong2 p2 = xq[12], p3 = xq[13];
        xq += 8;

        ull t;
        // ci=0
        t = dup2(w0.x);
        acc[0][0] = fma2(t, q0.x, acc[0][0]); acc[0][1] = fma2(t, q0.y, acc[0][1]);
        acc[0][2] = fma2(t, q1.x, acc[0][2]); acc[0][3] = fma2(t, q1.y, acc[0][3]);
        t = dup2(w0.y);
        acc[0][0] = fma2(t, q2.x, acc[0][0]); acc[0][1] = fma2(t, q2.y, acc[0][1]);
        acc[0][2] = fma2(t, q3.x, acc[0][2]); acc[0][3] = fma2(t, q3.y, acc[0][3]);
        // ci=1
        t = dup2(w0.z);
        acc[1][0] = fma2(t, q0.x, acc[1][0]); acc[1][1] = fma2(t, q0.y, acc[1][1]);
        acc[1][2] = fma2(t, q1.x, acc[1][2]); acc[1][3] = fma2(t, q1.y, acc[1][3]);
        t = dup2(w0.w);
        acc[1][0] = fma2(t, q2.x, acc[1][0]); acc[1][1] = fma2(t, q2.y, acc[1][1]);
        acc[1][2] = fma2(t, q3.x, acc[1][2]); acc[1][3] = fma2(t, q3.y, acc[1][3]);
        // ci=2
        t = dup2(w1.x);
        acc[2][0] = fma2(t, q0.x, acc[2][0]); acc[2][1] = fma2(t, q0.y, acc[2][1]);
        acc[2][2] = fma2(t, q1.x, acc[2][2]); acc[2][3] = fma2(t, q1.y, acc[2][3]);
        t = dup2(w1.y);
        acc[2][0] = fma2(t, q2.x, acc[2][0]); acc[2][1] = fma2(t, q2.y, acc[2][1]);
        acc[2][2] = fma2(t, q3.x, acc[2][2]); acc[2][3] = fma2(t, q3.y, acc[2][3]);
        // ci=3
        t = dup2(w1.z);
        acc[3][0] = fma2(t, q0.x, acc[3][0]); acc[3][1] = fma2(t, q0.y, acc[3][1]);
        acc[3][2] = fma2(t, q1.x, acc[3][2]); acc[3][3] = fma2(t, q1.y, acc[3][3]);
        t = dup2(w1.w);
        acc[3][0] = fma2(t, q2.x, acc[3][0]); acc[3][1] = fma2(t, q2.y, acc[3][1]);
        acc[3][2] = fma2(t, q3.x, acc[3][2]); acc[3][3] = fma2(t, q3.y, acc[3][3]);
        // ci=4
        t = dup2(w2.x);
        acc[4][0] = fma2(t, q0.x, acc[4][0]); acc[4][1] = fma2(t, q0.y, acc[4][1]);
        acc[4][2] = fma2(t, q1.x, acc[4][2]); acc[4][3] = fma2(t, q1.y, acc[4][3]);
        t = dup2(w2.y);
        acc[4][0] = fma2(t, q2.x, acc[4][0]); acc[4][1] = fma2(t, q2.y, acc[4][1]);
        acc[4][2] = fma2(t, q3.x, acc[4][2]); acc[4][3] = fma2(t, q3.y, acc[4][3]);
        // ci=5
        t = dup2(w2.z);
        acc[5][0] = fma2(t, q0.x, acc[5][0]); acc[5][1] = fma2(t, q0.y, acc[5][1]);
        acc[5][2] = fma2(t, q1.x, acc[5][2]); acc[5][3] = fma2(t, q1.y, acc[5][3]);
        t = dup2(w2.w);
        acc[5][0] = fma2(t, q2.x, acc[5][0]); acc[5][1] = fma2(t, q2.y, acc[5][1]);
        acc[5][2] = fma2(t, q3.x, acc[5][2]); acc[5][3] = fma2(t, q3.y, acc[5][3]);
        // ci=6
        t = dup2(w3.x);
        acc[6][0] = fma2(t, q0.x, acc[6][0]); acc[6][1] = fma2(t, q0.y, acc[6][1]);
        acc[6][2] = fma2(t, q1.x, acc[6][2]); acc[6][3] = fma2(t, q1.y, acc[6][3]);
        t = dup2(w3.y);
        acc[6][0] = fma2(t, q2.x, acc[6][0]); acc[6][1] = fma2(t, q2.y, acc[6][1]);
        acc[6][2] = fma2(t, q3.x, acc[6][2]); acc[6][3] = fma2(t, q3.y, acc[6][3]);
        // ci=7
        t = dup2(w3.z);
        acc[7][0] = fma2(t, q0.x, acc[7][0]); acc[7][1] = fma2(t, q0.y, acc[7][1]);
        acc[7][2] = fma2(t, q1.x, acc[7][2]); acc[7][3] = fma2(t, q1.y, acc[7][3]);
        t = dup2(w3.w);
        acc[7][0] = fma2(t, q2.x, acc[7][0]); acc[7][1] = fma2(t, q2.y, acc[7][1]);
        acc[7][2] = fma2(t, q3.x, acc[7][2]); acc[7][3] = fma2(t, q3.y, acc[7][3]);

        w0 = n0; w1 = n1; w2 = n2; w3 = n3;
        q0 = p0; q1 = p1; q2 = p2; q3 = p3;
    }

    // write 8 rows x 8 cols: two float4 STS per row
#pragma unroll
    for (int rp = 0; rp < 4; rp++) {
        float la[8], ha[8];
#pragma unroll
        for (int ci = 0; ci < 8; ci++) unpack2(acc[ci][rp], la[ci], ha[ci]);
        int row0 = rg * 8 + 2 * rp;
        float* d0 = gbuf + row0 * GSTR + c0;
        float* d1 = d0 + GSTR;
        *(float4*)(d0)     = make_float4(la[0], la[1], la[2], la[3]);
        *(float4*)(d0 + 4) = make_float4(la[4], la[5], la[6], la[7]);
        *(float4*)(d1)     = make_float4(ha[0], ha[1], ha[2], ha[3]);
        *(float4*)(d1 + 4) = make_float4(ha[4], ha[5], ha[6], ha[7]);
    }
}

// Small MLP layer over the CTA's 16 rows (head only; negligible cost)
__device__ __forceinline__ void mlp_layer(const float* __restrict__ vin, int Din,
                                          const float* __restrict__ W, const float* __restrict__ b,
                                          float* __restrict__ vout, int Dout, bool relu, int tid)
{
    for (int e = tid; e < ROWS * Dout; e += NTHREADS) {
        int r = e / Dout, o = e - r * Dout;
        const float* w = W + o * Din;
        const float* vi = vin + r * Din;
        float s = b[o];
        for (int i = 0; i < Din; i += 4) {
            s += w[i] * vi[i] + w[i + 1] * vi[i + 1] + w[i + 2] * vi[i + 2] + w[i + 3] * vi[i + 3];
        }
        vout[e] = relu ? fmaxf(s, 0.f) : s;
    }
    __syncthreads();
}

// ---------------------------------------------------------------------------
__global__ void __launch_bounds__(NTHREADS, 1)
dfmnet_main(const float* __restrict__ x,
            const float* __restrict__ Wk0, const float* __restrict__ bk0,
            const float* __restrict__ Wk1, const float* __restrict__ bk1,
            const float* __restrict__ Wk2, const float* __restrict__ bk2,
            const float* __restrict__ Wk3, const float* __restrict__ bk3,
            const float* __restrict__ Wk4, const float* __restrict__ bk4,
            const float* __restrict__ Wk5, const float* __restrict__ bk5,
            float* __restrict__ out, int Bn)
{
    extern __shared__ float sm[];
    float* xh    = sm;                    // [KROWS][16]
    float* gates = sm + KROWS * ROWS;     // 2 partial buffers [16][GSTR] each

    const int tid = threadIdx.x;
    const int kg  = tid >> 7;             // k-group 0/1 (4 warps each)
    const int rg  = (tid >> 6) & 1;       // row-group 0/1 (uniform per warp)
    const int cs  = tid & 63;             // col-strip: cols cs*8..cs*8+7
    const int b0  = blockIdx.x * ROWS;

    for (int e = tid; e < KROWS * ROWS; e += NTHREADS) xh[e] = 0.f;
    float c1r[8], c2r[8];
#pragma unroll
    for (int p = 0; p < 8; p++) { c1r[p] = 0.f; c2r[p] = 0.f; }

    // per-thread x element coordinates (4 elements: e = tid + q*256)
    const float* xbase = x + (size_t)b0 * T_SEQ * I_IN;
    int xrr[4], xkk[4];
#pragma unroll
    for (int q = 0; q < 4; q++) {
        int e = tid + q * NTHREADS;
        xrr[q] = e >> 6; xkk[q] = e & 63;
    }

    // prologue: load + store x_0
    float xr[4];
#pragma unroll
    for (int q = 0; q < 4; q++)
        xr[q] = xbase[(size_t)xrr[q] * (T_SEQ * I_IN) + xkk[q]];
#pragma unroll
    for (int q = 0; q < 4; q++)
        xh[xkk[q] * ROWS + xrr[q]] = xr[q];
    __syncthreads();

    float* mybuf = gates + kg * BSTR;

    for (int t = 0; t < T_SEQ; t++) {
        // layer 1: K=192 -> 96 chunks, 48 per k-group  (reads x_t + h1_prev)
        gemm_gates(g_Wt1, g_b1, xh, mybuf, kg * 48, 48, rg, cs, kg == 0);
        __syncthreads();

        // layer 1 activation: h1 -> xh rows [64,192); sum 2 partials
#pragma unroll
        for (int p = 0; p < 8; p++) {
            int idx = tid + p * NTHREADS;          // 0..2047
            int j = idx >> 4, r = idx & 15;
            const float* gb = gates + r * GSTR + j;
            float pi = gb[0]   + gb[BSTR];
            float pf = gb[128] + gb[BSTR + 128];
            float pg = gb[256] + gb[BSTR + 256];
            float po = gb[384] + gb[BSTR + 384];
            float iv = sigf(pi);
            float fv = sigf(pf);
            float gv = tanhf_fast(pg);
            float ov = sigf(po);
            float c = fv * c1r[p] + iv * gv;
            c1r[p] = c;
            xh[(64 + j) * ROWS + r] = ov * tanhf_fast(c);
        }
        __syncthreads();

        // prefetch x_{t+1} into registers (clamped; long cover under GEMM2)
        {
            int tn = (t + 1 < T_SEQ) ? (t + 1) : (T_SEQ - 1);
#pragma unroll
            for (int q = 0; q < 4; q++)
                xr[q] = xbase[(size_t)xrr[q] * (T_SEQ * I_IN) + (size_t)tn * I_IN + xkk[q]];
        }

        // layer 2: K=256 -> 128 chunks, 64 per k-group; xh rows [64,320)
        gemm_gates(g_Wt2, g_b2, xh + 64 * ROWS, mybuf, kg * 64, 64, rg, cs, kg == 0);
        __syncthreads();

        // layer 2 activation: h2 -> xh rows [192,320)  +  store x_{t+1}
#pragma unroll
        for (int p = 0; p < 8; p++) {
            int idx = tid + p * NTHREADS;
            int j = idx >> 4, r = idx & 15;
            const float* gb = gates + r * GSTR + j;
            float pi = gb[0]   + gb[BSTR];
            float pf = gb[128] + gb[BSTR + 128];
            float pg = gb[256] + gb[BSTR + 256];
            float po = gb[384] + gb[BSTR + 384];
            float iv = sigf(pi);
            float fv = sigf(pf);
            float gv = tanhf_fast(pg);
            float ov = sigf(po);
            float c = fv * c2r[p] + iv * gv;
            c2r[p] = c;
            xh[(192 + j) * ROWS + r] = ov * tanhf_fast(c);
        }
#pragma unroll
        for (int q = 0; q < 4; q++)
            xh[xkk[q] * ROWS + xrr[q]] = xr[q];
        __syncthreads();   // orders h2 + x_{t+1} before next G1 / gates reuse
    }

    // ---- outputs: tuple (y, h2, r) flattened ----
    float* out_y  = out;                              // [Bn][64]
    float* out_h2 = out + (size_t)Bn * 64;            // [Bn][128]
    float* out_r  = out + (size_t)Bn * 192;           // [Bn][192]

    float* va = gates;              // [16][192]
    float* vb = gates + ROWS * 192; // [16][128]
    float* vc = vb + ROWS * 128;    // [16][128]
    for (int e = tid; e < ROWS * 192; e += NTHREADS) {
        int r = e / 192, j = e - r * 192;
        // x rows hold x_{T-1} (last prefetch clamps to T-1)
        float v = (j < 128) ? xh[(192 + j) * ROWS + r] : xh[(j - 128) * ROWS + r];
        va[e] = v;
        out_r[(size_t)(b0 + r) * 192 + j] = v;
        if (j < 128) out_h2[(size_t)(b0 + r) * 128 + j] = v;
    }
    __syncthreads();

    mlp_layer(va, 192, Wk0, bk0, vb, 128, true, tid);
    mlp_layer(vb, 128, Wk1, bk1, vc, 128, true, tid);
    mlp_layer(vc, 128, Wk2, bk2, vb, 128, true, tid);
    mlp_layer(vb, 128, Wk3, bk3, vc, 128, true, tid);
    mlp_layer(vc, 128, Wk4, bk4, vb, 128, true, tid);

    for (int e = tid; e < ROWS * 64; e += NTHREADS) {
        int r = e >> 6, o = e & 63;
        const float* w = Wk5 + o * 128;
        const float* vi = vb + r * 128;
        float s = bk5[o];
        for (int i = 0; i < 128; i += 4) {
            s += w[i] * vi[i] + w[i + 1] * vi[i + 1] + w[i + 2] * vi[i + 2] + w[i + 3] * vi[i + 3];
        }
        out_y[(size_t)(b0 + r) * 64 + o] = s;
    }
}

// ---------------------------------------------------------------------------
extern "C" void kernel_launch(void* const* d_in, const int* in_sizes, int n_in,
                              void* d_out, int out_size)
{
    const float* x    = (const float*)d_in[0];
    const float* Wih1 = (const float*)d_in[1];
    const float* Whh1 = (const float*)d_in[2];
    const float* bih1 = (const float*)d_in[3];
    const float* bhh1 = (const float*)d_in[4];
    const float* Wih2 = (const float*)d_in[5];
    const float* Whh2 = (const float*)d_in[6];
    const float* bih2 = (const float*)d_in[7];
    const float* bhh2 = (const float*)d_in[8];
    const float* Wk0 = (const float*)d_in[9];   const float* bk0 = (const float*)d_in[10];
    const float* Wk1 = (const float*)d_in[11];  const float* bk1 = (const float*)d_in[12];
    const float* Wk2 = (const float*)d_in[13];  const float* bk2 = (const float*)d_in[14];
    const float* Wk3 = (const float*)d_in[15];  const float* bk3 = (const float*)d_in[16];
    const float* Wk4 = (const float*)d_in[17];  const float* bk4 = (const float*)d_in[18];
    const float* Wk5 = (const float*)d_in[19];  const float* bk5 = (const float*)d_in[20];

    int Bn = in_sizes[0] / (T_SEQ * I_IN);
    int smem_bytes = (KROWS * ROWS + 2 * ROWS * GSTR) * (int)sizeof(float);  // 86528 B

    cudaFuncSetAttribute(dfmnet_main, cudaFuncAttributeMaxDynamicSharedMemorySize, smem_bytes);

    prep_kernel<<<208, 256>>>(Wih1, Whh1, bih1, bhh1, Wih2, Whh2, bih2, bhh2);
    dfmnet_main<<<Bn / ROWS, NTHREADS, smem_bytes>>>(
        x, Wk0, bk0, Wk1, bk1, Wk2, bk2, Wk3, bk3, Wk4, bk4, Wk5, bk5,
        (float*)d_out, Bn);
}

// round 15
// speedup vs baseline: 1.3296x; 1.0124x over previous
#include <cuda_runtime.h>

// ---------------------------------------------------------------------------
// DFMNET: 2-layer LSTM (B=2048, T=256, I=64, H=128) + 6-layer MLP head.
// R15 = R10 (best: 8 cols x 8 rows/thread, 256 thr, split-K 2, coalesced
// [chunk][j][cs][float4] weights) + DEPTH-2 weight prefetch.
// Ledger from R10/R14: both warps/SMSP go ineligible ~20K cyc/step because
// the depth-1 prefetch window (1 chunk ~ 256 cyc) < L2 hit latency @NAT
// (~400-450 cyc). Three ring stages give a 2-chunk (~512 cyc) LDG->consume
// distance, covering L2. +2 padded chunks keep the tail branchless.
// ---------------------------------------------------------------------------

#define T_SEQ    256
#define I_IN     64
#define H_HID    128
#define ROWS     16            // batch rows per CTA
#define NTHREADS 256
#define KROWS    320           // xh rows: [x(64) | h1(128) | h2(128)]
#define GSTR     516           // gate-buffer row stride (floats)
#define BSTR     (ROWS * GSTR) // per-partial-buffer stride (floats)

typedef unsigned long long ull;

// Weights: [chunk][j=0..3][cs=0..63][4 floats]; float4 j of strip cs =
// (c_{2j}k0, c_{2j}k1, c_{2j+1}k0, c_{2j+1}k1) for cols cs*8..cs*8+7,
// k = 2c, 2c+1. +2 zero-padded chunks so the depth-2 prefetch never branches.
__device__ __align__(16) float g_Wt1[(96 + 2) * 1024];    // K=192 -> 96 chunks
__device__ __align__(16) float g_Wt2[(128 + 2) * 1024];   // K=256 -> 128 chunks
__device__ float g_b1[512];
__device__ float g_b2[512];

// ---- packed fp32x2 helpers ----
__device__ __forceinline__ ull fma2(ull a, ull b, ull c) {
    ull d;
    asm("fma.rn.f32x2 %0, %1, %2, %3;" : "=l"(d) : "l"(a), "l"(b), "l"(c));
    return d;
}
__device__ __forceinline__ void unpack2(ull v, float& lo, float& hi) {
    unsigned a, b;
    asm("mov.b64 {%0, %1}, %2;" : "=r"(a), "=r"(b) : "l"(v));
    lo = __uint_as_float(a); hi = __uint_as_float(b);
}
__device__ __forceinline__ ull dup2(float w) {
    ull r; unsigned u = __float_as_uint(w);
    asm("mov.b64 %0, {%1, %1};" : "=l"(r) : "r"(u));
    return r;
}

__device__ __forceinline__ float sigf(float v) {
    return __fdividef(1.f, 1.f + __expf(-v));
}
__device__ __forceinline__ float tanhf_fast(float v) {
    float z = fminf(fmaxf(v, -15.f), 15.f);
    float e = __expf(-2.f * z);
    return __fdividef(1.f - e, 1.f + e);
}

// ---------------------------------------------------------------------------
// Weight repack (same layout as R10): [chunk][j][cs][f]
//   e = c*1024 + j*256 + cs*4 + f ;  ci = j*2 + (f>>1), s = f&1
//   g = cs*8 + ci ; k = 2c + s  (k >= K -> 0 pad)
// ---------------------------------------------------------------------------
__global__ void prep_kernel(const float* __restrict__ Wih1, const float* __restrict__ Whh1,
                            const float* __restrict__ bih1, const float* __restrict__ bhh1,
                            const float* __restrict__ Wih2, const float* __restrict__ Whh2,
                            const float* __restrict__ bih2, const float* __restrict__ bhh2)
{
    int tid = blockIdx.x * blockDim.x + threadIdx.x;
    int stride = gridDim.x * blockDim.x;
    if (tid < 512) {
        g_b1[tid] = bih1[tid] + bhh1[tid];
        g_b2[tid] = bih2[tid] + bhh2[tid];
    }
    for (int e = tid; e < 98 * 1024; e += stride) {
        int c = e >> 10, r = e & 1023;
        int j = r >> 8, cs = (r >> 2) & 63, f = r & 3;
        int ci = j * 2 + (f >> 1), s = f & 1;
        int g = cs * 8 + ci;
        int k = 2 * c + s;
        float w = 0.f;
        if (k < 192) w = (k < 64) ? Wih1[g * 64 + k] : Whh1[g * 128 + (k - 64)];
        g_Wt1[e] = w;
    }
    for (int e = tid; e < 130 * 1024; e += stride) {
        int c = e >> 10, r = e & 1023;
        int j = r >> 8, cs = (r >> 2) & 63, f = r & 3;
        int ci = j * 2 + (f >> 1), s = f & 1;
        int g = cs * 8 + ci;
        int k = 2 * c + s;
        float w = 0.f;
        if (k < 256) w = (k < 128) ? Wih2[g * 128 + k] : Whh2[g * 128 + (k - 128)];
        g_Wt2[e] = w;
    }
}

// ---------------------------------------------------------------------------
// Partial gate GEMM over chunk range [cb, cb+nc):
//   gbuf[16][GSTR] = (bias?) + xh-slice @ Wt-slice for this thread's
//   8 cols (cs*8..cs*8+7) x 8 rows (rg*8..rg*8+7).
// acc[ci][rp] = f32x2 over rows (rg*8+2rp, rg*8+2rp+1), col cs*8+ci.
// DEPTH-2 weight ring: wa = chunk c (consumed), wb = c+1, load c+2 each
// iteration -> LDG->consume distance ~512 cyc > L2@NAT (~450).
// Per chunk/thread: 4 coalesced LDG.128, 4 broadcast LDS.128, 16 dup MOVs,
// 64 FFMA2 (the binder).
// ---------------------------------------------------------------------------
__device__ __forceinline__ void gemm_gates(const float* __restrict__ Wt,
                                           const float* __restrict__ bias,
                                           const float* __restrict__ xh,   // [k][16]
                                           float* __restrict__ gbuf,       // [16][GSTR]
                                           int cb, int nc, int rg, int cs, bool add_bias)
{
    const int c0 = cs * 8;
    ull acc[8][4];
    if (add_bias) {
#pragma unroll
        for (int ci = 0; ci < 8; ci++) {
            ull b = dup2(bias[c0 + ci]);
#pragma unroll
            for (int rp = 0; rp < 4; rp++) acc[ci][rp] = b;
        }
    } else {
#pragma unroll
        for (int ci = 0; ci < 8; ci++)
#pragma unroll
            for (int rp = 0; rp < 4; rp++) acc[ci][rp] = 0ull;
    }

    // depth-2 ring: wa (current), wb (next); prefetch c+2 each iteration
    const float4* Wp = (const float4*)Wt + cb * 256 + cs;
    float4 wa0 = Wp[0],   wa1 = Wp[64],  wa2 = Wp[128], wa3 = Wp[192];
    float4 wb0 = Wp[256], wb1 = Wp[320], wb2 = Wp[384], wb3 = Wp[448];
    const ulonglong2* xq = (const ulonglong2*)(xh + cb * 32 + rg * 8);

#pragma unroll 4
    for (int c = 0; c < nc; c++) {
        // prefetch chunk c+2 (padded tail: always valid memory)
        float4 wc0 = Wp[512], wc1 = Wp[576], wc2 = Wp[640], wc3 = Wp[704];
        Wp += 256;
        // this thread's 8 rows for k=2c (q0,q1) and k=2c+1 (q2,q3); broadcast
        ulonglong2 q0 = xq[0], q1 = xq[1];
        ulonglong2 q2 = xq[4], q3 = xq[5];
        xq += 8;

        ull t;
        // ci=0
        t = dup2(wa0.x);
        acc[0][0] = fma2(t, q0.x, acc[0][0]); acc[0][1] = fma2(t, q0.y, acc[0][1]);
        acc[0][2] = fma2(t, q1.x, acc[0][2]); acc[0][3] = fma2(t, q1.y, acc[0][3]);
        t = dup2(wa0.y);
        acc[0][0] = fma2(t, q2.x, acc[0][0]); acc[0][1] = fma2(t, q2.y, acc[0][1]);
        acc[0][2] = fma2(t, q3.x, acc[0][2]); acc[0][3] = fma2(t, q3.y, acc[0][3]);
        // ci=1
        t = dup2(wa0.z);
        acc[1][0] = fma2(t, q0.x, acc[1][0]); acc[1][1] = fma2(t, q0.y, acc[1][1]);
        acc[1][2] = fma2(t, q1.x, acc[1][2]); acc[1][3] = fma2(t, q1.y, acc[1][3]);
        t = dup2(wa0.w);
        acc[1][0] = fma2(t, q2.x, acc[1][0]); acc[1][1] = fma2(t, q2.y, acc[1][1]);
        acc[1][2] = fma2(t, q3.x, acc[1][2]); acc[1][3] = fma2(t, q3.y, acc[1][3]);
        // ci=2
        t = dup2(wa1.x);
        acc[2][0] = fma2(t, q0.x, acc[2][0]); acc[2][1] = fma2(t, q0.y, acc[2][1]);
        acc[2][2] = fma2(t, q1.x, acc[2][2]); acc[2][3] = fma2(t, q1.y, acc[2][3]);
        t = dup2(wa1.y);
        acc[2][0] = fma2(t, q2.x, acc[2][0]); acc[2][1] = fma2(t, q2.y, acc[2][1]);
        acc[2][2] = fma2(t, q3.x, acc[2][2]); acc[2][3] = fma2(t, q3.y, acc[2][3]);
        // ci=3
        t = dup2(wa1.z);
        acc[3][0] = fma2(t, q0.x, acc[3][0]); acc[3][1] = fma2(t, q0.y, acc[3][1]);
        acc[3][2] = fma2(t, q1.x, acc[3][2]); acc[3][3] = fma2(t, q1.y, acc[3][3]);
        t = dup2(wa1.w);
        acc[3][0] = fma2(t, q2.x, acc[3][0]); acc[3][1] = fma2(t, q2.y, acc[3][1]);
        acc[3][2] = fma2(t, q3.x, acc[3][2]); acc[3][3] = fma2(t, q3.y, acc[3][3]);
        // ci=4
        t = dup2(wa2.x);
        acc[4][0] = fma2(t, q0.x, acc[4][0]); acc[4][1] = fma2(t, q0.y, acc[4][1]);
        acc[4][2] = fma2(t, q1.x, acc[4][2]); acc[4][3] = fma2(t, q1.y, acc[4][3]);
        t = dup2(wa2.y);
        acc[4][0] = fma2(t, q2.x, acc[4][0]); acc[4][1] = fma2(t, q2.y, acc[4][1]);
        acc[4][2] = fma2(t, q3.x, acc[4][2]); acc[4][3] = fma2(t, q3.y, acc[4][3]);
        // ci=5
        t = dup2(wa2.z);
        acc[5][0] = fma2(t, q0.x, acc[5][0]); acc[5][1] = fma2(t, q0.y, acc[5][1]);
        acc[5][2] = fma2(t, q1.x, acc[5][2]); acc[5][3] = fma2(t, q1.y, acc[5][3]);
        t = dup2(wa2.w);
        acc[5][0] = fma2(t, q2.x, acc[5][0]); acc[5][1] = fma2(t, q2.y, acc[5][1]);
        acc[5][2] = fma2(t, q3.x, acc[5][2]); acc[5][3] = fma2(t, q3.y, acc[5][3]);
        // ci=6
        t = dup2(wa3.x);
        acc[6][0] = fma2(t, q0.x, acc[6][0]); acc[6][1] = fma2(t, q0.y, acc[6][1]);
        acc[6][2] = fma2(t, q1.x, acc[6][2]); acc[6][3] = fma2(t, q1.y, acc[6][3]);
        t = dup2(wa3.y);
        acc[6][0] = fma2(t, q2.x, acc[6][0]); acc[6][1] = fma2(t, q2.y, acc[6][1]);
        acc[6][2] = fma2(t, q3.x, acc[6][2]); acc[6][3] = fma2(t, q3.y, acc[6][3]);
        // ci=7
        t = dup2(wa3.z);
        acc[7][0] = fma2(t, q0.x, acc[7][0]); acc[7][1] = fma2(t, q0.y, acc[7][1]);
        acc[7][2] = fma2(t, q1.x, acc[7][2]); acc[7][3] = fma2(t, q1.y, acc[7][3]);
        t = dup2(wa3.w);
        acc[7][0] = fma2(t, q2.x, acc[7][0]); acc[7][1] = fma2(t, q2.y, acc[7][1]);
        acc[7][2] = fma2(t, q3.x, acc[7][2]); acc[7][3] = fma2(t, q3.y, acc[7][3]);

        wa0 = wb0; wa1 = wb1; wa2 = wb2; wa3 = wb3;
        wb0 = wc0; wb1 = wc1; wb2 = wc2; wb3 = wc3;
    }

    // write 8 rows x 8 cols: two float4 STS per row
#pragma unroll
    for (int rp = 0; rp < 4; rp++) {
        float la[8], ha[8];
#pragma unroll
        for (int ci = 0; ci < 8; ci++) unpack2(acc[ci][rp], la[ci], ha[ci]);
        int row0 = rg * 8 + 2 * rp;
        float* d0 = gbuf + row0 * GSTR + c0;
        float* d1 = d0 + GSTR;
        *(float4*)(d0)     = make_float4(la[0], la[1], la[2], la[3]);
        *(float4*)(d0 + 4) = make_float4(la[4], la[5], la[6], la[7]);
        *(float4*)(d1)     = make_float4(ha[0], ha[1], ha[2], ha[3]);
        *(float4*)(d1 + 4) = make_float4(ha[4], ha[5], ha[6], ha[7]);
    }
}

// Small MLP layer over the CTA's 16 rows (head only; negligible cost)
__device__ __forceinline__ void mlp_layer(const float* __restrict__ vin, int Din,
                                          const float* __restrict__ W, const float* __restrict__ b,
                                          float* __restrict__ vout, int Dout, bool relu, int tid)
{
    for (int e = tid; e < ROWS * Dout; e += NTHREADS) {
        int r = e / Dout, o = e - r * Dout;
        const float* w = W + o * Din;
        const float* vi = vin + r * Din;
        float s = b[o];
        for (int i = 0; i < Din; i += 4) {
            s += w[i] * vi[i] + w[i + 1] * vi[i + 1] + w[i + 2] * vi[i + 2] + w[i + 3] * vi[i + 3];
        }
        vout[e] = relu ? fmaxf(s, 0.f) : s;
    }
    __syncthreads();
}

// ---------------------------------------------------------------------------
__global__ void __launch_bounds__(NTHREADS, 1)
dfmnet_main(const float* __restrict__ x,
            const float* __restrict__ Wk0, const float* __restrict__ bk0,
            const float* __restrict__ Wk1, const float* __restrict__ bk1,
            const float* __restrict__ Wk2, const float* __restrict__ bk2,
            const float* __restrict__ Wk3, const float* __restrict__ bk3,
            const float* __restrict__ Wk4, const float* __restrict__ bk4,
            const float* __restrict__ Wk5, const float* __restrict__ bk5,
            float* __restrict__ out, int Bn)
{
    extern __shared__ float sm[];
    float* xh    = sm;                    // [KROWS][16]
    float* gates = sm + KROWS * ROWS;     // 2 partial buffers [16][GSTR] each

    const int tid = threadIdx.x;
    const int kg  = tid >> 7;             // k-group 0/1 (4 warps each)
    const int rg  = (tid >> 6) & 1;       // row-group 0/1 (uniform per warp)
    const int cs  = tid & 63;             // col-strip: cols cs*8..cs*8+7
    const int b0  = blockIdx.x * ROWS;

    for (int e = tid; e < KROWS * ROWS; e += NTHREADS) xh[e] = 0.f;
    float c1r[8], c2r[8];
#pragma unroll
    for (int p = 0; p < 8; p++) { c1r[p] = 0.f; c2r[p] = 0.f; }
    __syncthreads();

    const float* xbase = x + (size_t)b0 * T_SEQ * I_IN;
    float* mybuf = gates + kg * BSTR;

    for (int t = 0; t < T_SEQ; t++) {
        // load x_t (16 rows x 64) transposed into xh rows [0,64)
#pragma unroll
        for (int q = 0; q < 4; q++) {
            int e = tid + q * NTHREADS;            // 0..1023
            int r = e >> 6, k = e & 63;
            xh[k * ROWS + r] = xbase[(size_t)r * (T_SEQ * I_IN) + t * I_IN + k];
        }
        __syncthreads();

        // layer 1: K=192 -> 96 chunks, 48 per k-group
        gemm_gates(g_Wt1, g_b1, xh, mybuf, kg * 48, 48, rg, cs, kg == 0);
        __syncthreads();

        // layer 1 activation: h1 -> xh rows [64,192); sum 2 partials
#pragma unroll
        for (int p = 0; p < 8; p++) {
            int idx = tid + p * NTHREADS;          // 0..2047
            int j = idx >> 4, r = idx & 15;
            const float* gb = gates + r * GSTR + j;
            float pi = gb[0]   + gb[BSTR];
            float pf = gb[128] + gb[BSTR + 128];
            float pg = gb[256] + gb[BSTR + 256];
            float po = gb[384] + gb[BSTR + 384];
            float iv = sigf(pi);
            float fv = sigf(pf);
            float gv = tanhf_fast(pg);
            float ov = sigf(po);
            float c = fv * c1r[p] + iv * gv;
            c1r[p] = c;
            xh[(64 + j) * ROWS + r] = ov * tanhf_fast(c);
        }
        __syncthreads();

        // layer 2: K=256 -> 128 chunks, 64 per k-group; xh rows [64,320)
        gemm_gates(g_Wt2, g_b2, xh + 64 * ROWS, mybuf, kg * 64, 64, rg, cs, kg == 0);
        __syncthreads();

        // layer 2 activation: h2 -> xh rows [192,320)
#pragma unroll
        for (int p = 0; p < 8; p++) {
            int idx = tid + p * NTHREADS;
            int j = idx >> 4, r = idx & 15;
            const float* gb = gates + r * GSTR + j;
            float pi = gb[0]   + gb[BSTR];
            float pf = gb[128] + gb[BSTR + 128];
            float pg = gb[256] + gb[BSTR + 256];
            float po = gb[384] + gb[BSTR + 384];
            float iv = sigf(pi);
            float fv = sigf(pf);
            float gv = tanhf_fast(pg);
            float ov = sigf(po);
            float c = fv * c2r[p] + iv * gv;
            c2r[p] = c;
            xh[(192 + j) * ROWS + r] = ov * tanhf_fast(c);
        }
        // next iter's x-load writes disjoint smem; its __syncthreads orders
        // these h2 writes (and this phase's gates reads) before reuse.
    }
    __syncthreads();

    // ---- outputs: tuple (y, h2, r) flattened ----
    float* out_y  = out;                              // [Bn][64]
    float* out_h2 = out + (size_t)Bn * 64;            // [Bn][128]
    float* out_r  = out + (size_t)Bn * 192;           // [Bn][192]

    float* va = gates;              // [16][192]
    float* vb = gates + ROWS * 192; // [16][128]
    float* vc = vb + ROWS * 128;    // [16][128]
    for (int e = tid; e < ROWS * 192; e += NTHREADS) {
        int r = e / 192, j = e - r * 192;
        float v = (j < 128) ? xh[(192 + j) * ROWS + r] : xh[(j - 128) * ROWS + r];
        va[e] = v;
        out_r[(size_t)(b0 + r) * 192 + j] = v;
        if (j < 128) out_h2[(size_t)(b0 + r) * 128 + j] = v;
    }
    __syncthreads();

    mlp_layer(va, 192, Wk0, bk0, vb, 128, true, tid);
    mlp_layer(vb, 128, Wk1, bk1, vc, 128, true, tid);
    mlp_layer(vc, 128, Wk2, bk2, vb, 128, true, tid);
    mlp_layer(vb, 128, Wk3, bk3, vc, 128, true, tid);
    mlp_layer(vc, 128, Wk4, bk4, vb, 128, true, tid);

    for (int e = tid; e < ROWS * 64; e += NTHREADS) {
        int r = e >> 6, o = e & 63;
        const float* w = Wk5 + o * 128;
        const float* vi = vb + r * 128;
        float s = bk5[o];
        for (int i = 0; i < 128; i += 4) {
            s += w[i] * vi[i] + w[i + 1] * vi[i + 1] + w[i + 2] * vi[i + 2] + w[i + 3] * vi[i + 3];
        }
        out_y[(size_t)(b0 + r) * 64 + o] = s;
    }
}

// ---------------------------------------------------------------------------
extern "C" void kernel_launch(void* const* d_in, const int* in_sizes, int n_in,
                              void* d_out, int out_size)
{
    const float* x    = (const float*)d_in[0];
    const float* Wih1 = (const float*)d_in[1];
    const float* Whh1 = (const float*)d_in[2];
    const float* bih1 = (const float*)d_in[3];
    const float* bhh1 = (const float*)d_in[4];
    const float* Wih2 = (const float*)d_in[5];
    const float* Whh2 = (const float*)d_in[6];
    const float* bih2 = (const float*)d_in[7];
    const float* bhh2 = (const float*)d_in[8];
    const float* Wk0 = (const float*)d_in[9];   const float* bk0 = (const float*)d_in[10];
    const float* Wk1 = (const float*)d_in[11];  const float* bk1 = (const float*)d_in[12];
    const float* Wk2 = (const float*)d_in[13];  const float* bk2 = (const float*)d_in[14];
    const float* Wk3 = (const float*)d_in[15];  const float* bk3 = (const float*)d_in[16];
    const float* Wk4 = (const float*)d_in[17];  const float* bk4 = (const float*)d_in[18];
    const float* Wk5 = (const float*)d_in[19];  const float* bk5 = (const float*)d_in[20];

    int Bn = in_sizes[0] / (T_SEQ * I_IN);
    int smem_bytes = (KROWS * ROWS + 2 * ROWS * GSTR) * (int)sizeof(float);  // 86528 B

    cudaFuncSetAttribute(dfmnet_main, cudaFuncAttributeMaxDynamicSharedMemorySize, smem_bytes);

    prep_kernel<<<208, 256>>>(Wih1, Whh1, bih1, bhh1, Wih2, Whh2, bih2, bhh2);
    dfmnet_main<<<Bn / ROWS, NTHREADS, smem_bytes>>>(
        x, Wk0, bk0, Wk1, bk1, Wk2, bk2, Wk3, bk3, Wk4, bk4, Wk5, bk5,
        (float*)d_out, Bn);
}

// round 16
// speedup vs baseline: 1.3788x; 1.0370x over previous
#include <cuda_runtime.h>

// ---------------------------------------------------------------------------
// DFMNET: 2-layer LSTM (B=2048, T=256, I=64, H=128) + 6-layer MLP head.
// R16: the kernel is AT the FFMA2 RF-banking floor (rt=3: 3 distinct 64-bit
// operands = 3 even-bank reads; measured 3.0 cyc/FFMA2). Only lever left:
// work per SM. Grid 128 -> 148 (full chip): CTA = 14 rows (124 CTAs) or 13
// rows (24 CTAs, one isolated junk row). Thread = 8 cols x 7 row-pairs over
// K/4 (split-K 4). Weight layout/loads identical to R10 (coalesced
// [chunk][j][cs][float4], depth-1 ring). LSTM c-state lives in smem.
// Per-SMSP FFMA2/step: 14336 -> 12544 (-12.5%) and 148/148 SMs busy.
// ---------------------------------------------------------------------------

#define T_SEQ    256
#define I_IN     64
#define H_HID    128
#define MROWS    14            // max rows per CTA
#define SLOT     16            // row-slot stride in xh (floats)
#define NTHREADS 256
#define KROWS    320           // xh rows: [x(64) | h1(128) | h2(128)]
#define GSTR     516           // gate-buffer row stride (floats)
#define BSTR     (MROWS * GSTR) // per-partial-buffer stride (floats)
#define NGRID    148

typedef unsigned long long ull;

// Weights: [chunk][j=0..3][cs=0..63][4 floats]; float4 j of strip cs =
// (c_{2j}k0, c_{2j}k1, c_{2j+1}k0, c_{2j+1}k1) for cols cs*8..cs*8+7,
// k = 2c, 2c+1. +1 zero-padded chunk so depth-1 prefetch never branches.
__device__ __align__(16) float g_Wt1[(96 + 1) * 1024];    // K=192 -> 96 chunks
__device__ __align__(16) float g_Wt2[(128 + 1) * 1024];   // K=256 -> 128 chunks
__device__ float g_b1[512];
__device__ float g_b2[512];

// ---- packed fp32x2 helpers ----
__device__ __forceinline__ ull fma2(ull a, ull b, ull c) {
    ull d;
    asm("fma.rn.f32x2 %0, %1, %2, %3;" : "=l"(d) : "l"(a), "l"(b), "l"(c));
    return d;
}
__device__ __forceinline__ void unpack2(ull v, float& lo, float& hi) {
    unsigned a, b;
    asm("mov.b64 {%0, %1}, %2;" : "=r"(a), "=r"(b) : "l"(v));
    lo = __uint_as_float(a); hi = __uint_as_float(b);
}
__device__ __forceinline__ ull dup2(float w) {
    ull r; unsigned u = __float_as_uint(w);
    asm("mov.b64 %0, {%1, %1};" : "=l"(r) : "r"(u));
    return r;
}

__device__ __forceinline__ float sigf(float v) {
    return __fdividef(1.f, 1.f + __expf(-v));
}
__device__ __forceinline__ float tanhf_fast(float v) {
    float z = fminf(fmaxf(v, -15.f), 15.f);
    float e = __expf(-2.f * z);
    return __fdividef(1.f - e, 1.f + e);
}

// ---------------------------------------------------------------------------
// Weight repack (identical to R10): [chunk][j][cs][f]
//   e = c*1024 + j*256 + cs*4 + f ;  ci = j*2 + (f>>1), s = f&1
//   g = cs*8 + ci ; k = 2c + s  (k >= K -> 0 pad)
// ---------------------------------------------------------------------------
__global__ void prep_kernel(const float* __restrict__ Wih1, const float* __restrict__ Whh1,
                            const float* __restrict__ bih1, const float* __restrict__ bhh1,
                            const float* __restrict__ Wih2, const float* __restrict__ Whh2,
                            const float* __restrict__ bih2, const float* __restrict__ bhh2)
{
    int tid = blockIdx.x * blockDim.x + threadIdx.x;
    int stride = gridDim.x * blockDim.x;
    if (tid < 512) {
        g_b1[tid] = bih1[tid] + bhh1[tid];
        g_b2[tid] = bih2[tid] + bhh2[tid];
    }
    for (int e = tid; e < 97 * 1024; e += stride) {
        int c = e >> 10, r = e & 1023;
        int j = r >> 8, cs = (r >> 2) & 63, f = r & 3;
        int ci = j * 2 + (f >> 1), s = f & 1;
        int g = cs * 8 + ci;
        int k = 2 * c + s;
        float w = 0.f;
        if (k < 192) w = (k < 64) ? Wih1[g * 64 + k] : Whh1[g * 128 + (k - 64)];
        g_Wt1[e] = w;
    }
    for (int e = tid; e < 129 * 1024; e += stride) {
        int c = e >> 10, r = e & 1023;
        int j = r >> 8, cs = (r >> 2) & 63, f = r & 3;
        int ci = j * 2 + (f >> 1), s = f & 1;
        int g = cs * 8 + ci;
        int k = 2 * c + s;
        float w = 0.f;
        if (k < 256) w = (k < 128) ? Wih2[g * 128 + k] : Whh2[g * 128 + (k - 128)];
        g_Wt2[e] = w;
    }
}

// ---------------------------------------------------------------------------
// Partial gate GEMM over chunk range [cb, cb+nc):
//   gbuf[14][GSTR] = (bias?) + xh-slice @ Wt-slice for this thread's
//   8 cols (cs*8..cs*8+7) x ALL 14 row-slots (7 f32x2 pairs).
// Per chunk/thread: 4 coalesced LDG.128 (depth-1 ring), 6 LDS.128 + 2 LDS.64
// broadcasts, 16 dup MOVs (alu), 112 FFMA2 (the rt=3 binder).
// ---------------------------------------------------------------------------
__device__ __forceinline__ void gemm_gates(const float* __restrict__ Wt,
                                           const float* __restrict__ bias,
                                           const float* __restrict__ xh,   // [k][SLOT]
                                           float* __restrict__ gbuf,       // [14][GSTR]
                                           int cb, int nc, int cs, bool add_bias)
{
    const int c0 = cs * 8;
    ull acc[8][7];
    if (add_bias) {
#pragma unroll
        for (int ci = 0; ci < 8; ci++) {
            ull b = dup2(bias[c0 + ci]);
#pragma unroll
            for (int rp = 0; rp < 7; rp++) acc[ci][rp] = b;
        }
    } else {
#pragma unroll
        for (int ci = 0; ci < 8; ci++)
#pragma unroll
            for (int rp = 0; rp < 7; rp++) acc[ci][rp] = 0ull;
    }

    const float4* Wp = (const float4*)Wt + cb * 256 + cs;
    float4 w0 = Wp[0], w1 = Wp[64], w2 = Wp[128], w3 = Wp[192];
    const float* xb = xh + cb * (2 * SLOT);

#pragma unroll 2
    for (int c = 0; c < nc; c++) {
        // prefetch next chunk's weights (padded tail: always valid memory)
        float4 n0 = Wp[256], n1 = Wp[320], n2 = Wp[384], n3 = Wp[448];
        Wp += 256;
        // rows 0..13 for k = 2c (qe*) and k = 2c+1 (qo*); warp-broadcast
        const ulonglong2* xe2 = (const ulonglong2*)xb;
        const ull*        xe1 = (const ull*)xb;
        ulonglong2 ea = xe2[0], eb = xe2[1], ec = xe2[2];
        ull e6 = xe1[6];
        const ulonglong2* xo2 = (const ulonglong2*)(xb + SLOT);
        const ull*        xo1 = (const ull*)(xb + SLOT);
        ulonglong2 oa = xo2[0], ob = xo2[1], oc = xo2[2];
        ull o6 = xo1[6];
        xb += 2 * SLOT;

        ull qe0 = ea.x, qe1 = ea.y, qe2 = eb.x, qe3 = eb.y, qe4 = ec.x, qe5 = ec.y, qe6 = e6;
        ull qo0 = oa.x, qo1 = oa.y, qo2 = ob.x, qo3 = ob.y, qo4 = oc.x, qo5 = oc.y, qo6 = o6;

        float4 wj[4] = {w0, w1, w2, w3};
#pragma unroll
        for (int j = 0; j < 4; j++) {
            ull t;
            t = dup2(wj[j].x);   // col 2j, k even
            acc[2*j][0] = fma2(t, qe0, acc[2*j][0]);
            acc[2*j][1] = fma2(t, qe1, acc[2*j][1]);
            acc[2*j][2] = fma2(t, qe2, acc[2*j][2]);
            acc[2*j][3] = fma2(t, qe3, acc[2*j][3]);
            acc[2*j][4] = fma2(t, qe4, acc[2*j][4]);
            acc[2*j][5] = fma2(t, qe5, acc[2*j][5]);
            acc[2*j][6] = fma2(t, qe6, acc[2*j][6]);
            t = dup2(wj[j].y);   // col 2j, k odd
            acc[2*j][0] = fma2(t, qo0, acc[2*j][0]);
            acc[2*j][1] = fma2(t, qo1, acc[2*j][1]);
            acc[2*j][2] = fma2(t, qo2, acc[2*j][2]);
            acc[2*j][3] = fma2(t, qo3, acc[2*j][3]);
            acc[2*j][4] = fma2(t, qo4, acc[2*j][4]);
            acc[2*j][5] = fma2(t, qo5, acc[2*j][5]);
            acc[2*j][6] = fma2(t, qo6, acc[2*j][6]);
            t = dup2(wj[j].z);   // col 2j+1, k even
            acc[2*j+1][0] = fma2(t, qe0, acc[2*j+1][0]);
            acc[2*j+1][1] = fma2(t, qe1, acc[2*j+1][1]);
            acc[2*j+1][2] = fma2(t, qe2, acc[2*j+1][2]);
            acc[2*j+1][3] = fma2(t, qe3, acc[2*j+1][3]);
            acc[2*j+1][4] = fma2(t, qe4, acc[2*j+1][4]);
            acc[2*j+1][5] = fma2(t, qe5, acc[2*j+1][5]);
            acc[2*j+1][6] = fma2(t, qe6, acc[2*j+1][6]);
            t = dup2(wj[j].w);   // col 2j+1, k odd
            acc[2*j+1][0] = fma2(t, qo0, acc[2*j+1][0]);
            acc[2*j+1][1] = fma2(t, qo1, acc[2*j+1][1]);
            acc[2*j+1][2] = fma2(t, qo2, acc[2*j+1][2]);
            acc[2*j+1][3] = fma2(t, qo3, acc[2*j+1][3]);
            acc[2*j+1][4] = fma2(t, qo4, acc[2*j+1][4]);
            acc[2*j+1][5] = fma2(t, qo5, acc[2*j+1][5]);
            acc[2*j+1][6] = fma2(t, qo6, acc[2*j+1][6]);
        }
        w0 = n0; w1 = n1; w2 = n2; w3 = n3;
    }

    // write 14 rows x 8 cols: two float4 STS per row
#pragma unroll
    for (int rp = 0; rp < 7; rp++) {
        float la[8], ha[8];
#pragma unroll
        for (int ci = 0; ci < 8; ci++) unpack2(acc[ci][rp], la[ci], ha[ci]);
        float* d0 = gbuf + (2 * rp) * GSTR + c0;
        float* d1 = d0 + GSTR;
        *(float4*)(d0)     = make_float4(la[0], la[1], la[2], la[3]);
        *(float4*)(d0 + 4) = make_float4(la[4], la[5], la[6], la[7]);
        *(float4*)(d1)     = make_float4(ha[0], ha[1], ha[2], ha[3]);
        *(float4*)(d1 + 4) = make_float4(ha[4], ha[5], ha[6], ha[7]);
    }
}

// Small MLP layer over the CTA's rows (head only; negligible cost)
__device__ __forceinline__ void mlp_layer(const float* __restrict__ vin, int Din,
                                          const float* __restrict__ W, const float* __restrict__ b,
                                          float* __restrict__ vout, int Dout,
                                          bool relu, int tid, int myrows)
{
    for (int e = tid; e < myrows * Dout; e += NTHREADS) {
        int r = e / Dout, o = e - r * Dout;
        const float* w = W + o * Din;
        const float* vi = vin + r * Din;
        float s = b[o];
        for (int i = 0; i < Din; i += 4) {
            s += w[i] * vi[i] + w[i + 1] * vi[i + 1] + w[i + 2] * vi[i + 2] + w[i + 3] * vi[i + 3];
        }
        vout[e] = relu ? fmaxf(s, 0.f) : s;
    }
    __syncthreads();
}

// ---------------------------------------------------------------------------
__global__ void __launch_bounds__(NTHREADS, 1)
dfmnet_main(const float* __restrict__ x,
            const float* __restrict__ Wk0, const float* __restrict__ bk0,
            const float* __restrict__ Wk1, const float* __restrict__ bk1,
            const float* __restrict__ Wk2, const float* __restrict__ bk2,
            const float* __restrict__ Wk3, const float* __restrict__ bk3,
            const float* __restrict__ Wk4, const float* __restrict__ bk4,
            const float* __restrict__ Wk5, const float* __restrict__ bk5,
            float* __restrict__ out, int Bn)
{
    extern __shared__ float sm[];
    float* xh    = sm;                         // [KROWS][SLOT]
    float* gates = sm + KROWS * SLOT;          // 4 partial buffers [14][GSTR]
    float* c1s   = gates + 4 * BSTR;           // [14*128] LSTM1 cell state
    float* c2s   = c1s + MROWS * H_HID;        // [14*128] LSTM2 cell state

    const int tid = threadIdx.x;
    const int kg  = tid >> 6;             // k-group 0..3 (2 warps each)
    const int cs  = tid & 63;             // col-strip: cols cs*8..cs*8+7
    const int bx  = blockIdx.x;

    // row split: nhi CTAs of rhi rows, rest rhi-1 rows (rhi = ceil(Bn/148))
    const int rhi  = (Bn + NGRID - 1) / NGRID;
    const int nhi  = Bn - NGRID * (rhi - 1);
    const int myrows = (bx < nhi) ? rhi : (rhi - 1);
    const int b0     = (bx < nhi) ? bx * rhi : nhi * rhi + (bx - nhi) * (rhi - 1);

    for (int e = tid; e < KROWS * SLOT; e += NTHREADS) xh[e] = 0.f;
    for (int e = tid; e < MROWS * H_HID; e += NTHREADS) { c1s[e] = 0.f; c2s[e] = 0.f; }
    __syncthreads();

    const float* xbase = x + (size_t)b0 * T_SEQ * I_IN;
    float* mybuf = gates + kg * BSTR;

    for (int t = 0; t < T_SEQ; t++) {
        // load x_t (myrows x 64) transposed into xh rows [0,64)
        for (int e = tid; e < myrows * I_IN; e += NTHREADS) {
            int r = e >> 6, k = e & 63;
            xh[k * SLOT + r] = xbase[(size_t)r * (T_SEQ * I_IN) + t * I_IN + k];
        }
        __syncthreads();

        // layer 1: K=192 -> 96 chunks, 24 per k-group
        gemm_gates(g_Wt1, g_b1, xh, mybuf, kg * 24, 24, cs, kg == 0);
        __syncthreads();

        // layer 1 activation: h1 -> xh rows [64,192); sum 4 partials
#pragma unroll
        for (int p = 0; p < 7; p++) {
            int idx = tid + p * NTHREADS;          // 0..1791
            int r = idx >> 7, j = idx & 127;
            if (r < myrows) {
                const float* gb = gates + r * GSTR + j;
                float pi = gb[0]   + gb[BSTR]       + gb[2 * BSTR]       + gb[3 * BSTR];
                float pf = gb[128] + gb[BSTR + 128] + gb[2 * BSTR + 128] + gb[3 * BSTR + 128];
                float pg = gb[256] + gb[BSTR + 256] + gb[2 * BSTR + 256] + gb[3 * BSTR + 256];
                float po = gb[384] + gb[BSTR + 384] + gb[2 * BSTR + 384] + gb[3 * BSTR + 384];
                float iv = sigf(pi);
                float fv = sigf(pf);
                float gv = tanhf_fast(pg);
                float ov = sigf(po);
                float c = fv * c1s[idx] + iv * gv;
                c1s[idx] = c;
                xh[(64 + j) * SLOT + r] = ov * tanhf_fast(c);
            }
        }
        __syncthreads();

        // layer 2: K=256 -> 128 chunks, 32 per k-group; xh rows [64,320)
        gemm_gates(g_Wt2, g_b2, xh + 64 * SLOT, mybuf, kg * 32, 32, cs, kg == 0);
        __syncthreads();

        // layer 2 activation: h2 -> xh rows [192,320)
#pragma unroll
        for (int p = 0; p < 7; p++) {
            int idx = tid + p * NTHREADS;
            int r = idx >> 7, j = idx & 127;
            if (r < myrows) {
                const float* gb = gates + r * GSTR + j;
                float pi = gb[0]   + gb[BSTR]       + gb[2 * BSTR]       + gb[3 * BSTR];
                float pf = gb[128] + gb[BSTR + 128] + gb[2 * BSTR + 128] + gb[3 * BSTR + 128];
                float pg = gb[256] + gb[BSTR + 256] + gb[2 * BSTR + 256] + gb[3 * BSTR + 256];
                float po = gb[384] + gb[BSTR + 384] + gb[2 * BSTR + 384] + gb[3 * BSTR + 384];
                float iv = sigf(pi);
                float fv = sigf(pf);
                float gv = tanhf_fast(pg);
                float ov = sigf(po);
                float c = fv * c2s[idx] + iv * gv;
                c2s[idx] = c;
                xh[(192 + j) * SLOT + r] = ov * tanhf_fast(c);
            }
        }
        __syncthreads();
    }

    // ---- outputs: tuple (y, h2, r) flattened ----
    float* out_y  = out;                              // [Bn][64]
    float* out_h2 = out + (size_t)Bn * 64;            // [Bn][128]
    float* out_r  = out + (size_t)Bn * 192;           // [Bn][192]

    float* va = gates;               // [14][192]
    float* vb = gates + MROWS * 192; // [14][128]
    float* vc = vb + MROWS * 128;    // [14][128]
    for (int e = tid; e < myrows * 192; e += NTHREADS) {
        int r = e / 192, j = e - r * 192;
        // xh x-rows hold x_{T-1}; h2 rows hold final h2
        float v = (j < 128) ? xh[(192 + j) * SLOT + r] : xh[(j - 128) * SLOT + r];
        va[e] = v;
        out_r[(size_t)(b0 + r) * 192 + j] = v;
        if (j < 128) out_h2[(size_t)(b0 + r) * 128 + j] = v;
    }
    __syncthreads();

    mlp_layer(va, 192, Wk0, bk0, vb, 128, true, tid, myrows);
    mlp_layer(vb, 128, Wk1, bk1, vc, 128, true, tid, myrows);
    mlp_layer(vc, 128, Wk2, bk2, vb, 128, true, tid, myrows);
    mlp_layer(vb, 128, Wk3, bk3, vc, 128, true, tid, myrows);
    mlp_layer(vc, 128, Wk4, bk4, vb, 128, true, tid, myrows);

    for (int e = tid; e < myrows * 64; e += NTHREADS) {
        int r = e >> 6, o = e & 63;
        const float* w = Wk5 + o * 128;
        const float* vi = vb + r * 128;
        float s = bk5[o];
        for (int i = 0; i < 128; i += 4) {
            s += w[i] * vi[i] + w[i + 1] * vi[i + 1] + w[i + 2] * vi[i + 2] + w[i + 3] * vi[i + 3];
        }
        out_y[(size_t)(b0 + r) * 64 + o] = s;
    }
}

// ---------------------------------------------------------------------------
extern "C" void kernel_launch(void* const* d_in, const int* in_sizes, int n_in,
                              void* d_out, int out_size)
{
    const float* x    = (const float*)d_in[0];
    const float* Wih1 = (const float*)d_in[1];
    const float* Whh1 = (const float*)d_in[2];
    const float* bih1 = (const float*)d_in[3];
    const float* bhh1 = (const float*)d_in[4];
    const float* Wih2 = (const float*)d_in[5];
    const float* Whh2 = (const float*)d_in[6];
    const float* bih2 = (const float*)d_in[7];
    const float* bhh2 = (const float*)d_in[8];
    const float* Wk0 = (const float*)d_in[9];   const float* bk0 = (const float*)d_in[10];
    const float* Wk1 = (const float*)d_in[11];  const float* bk1 = (const float*)d_in[12];
    const float* Wk2 = (const float*)d_in[13];  const float* bk2 = (const float*)d_in[14];
    const float* Wk3 = (const float*)d_in[15];  const float* bk3 = (const float*)d_in[16];
    const float* Wk4 = (const float*)d_in[17];  const float* bk4 = (const float*)d_in[18];
    const float* Wk5 = (const float*)d_in[19];  const float* bk5 = (const float*)d_in[20];

    int Bn = in_sizes[0] / (T_SEQ * I_IN);
    // xh + 4 gate partials + c1 + c2
    int smem_bytes = (KROWS * SLOT + 4 * BSTR + 2 * MROWS * H_HID) * (int)sizeof(float); // 150400 B

    cudaFuncSetAttribute(dfmnet_main, cudaFuncAttributeMaxDynamicSharedMemorySize, smem_bytes);

    prep_kernel<<<208, 256>>>(Wih1, Whh1, bih1, bhh1, Wih2, Whh2, bih2, bhh2);
    dfmnet_main<<<NGRID, NTHREADS, smem_bytes>>>(
        x, Wk0, bk0, Wk1, bk1, Wk2, bk2, Wk3, bk3, Wk4, bk4, Wk5, bk5,
        (float*)d_out, Bn);
}

// round 17
// speedup vs baseline: 1.4677x; 1.0645x over previous
#include <cuda_runtime.h>

// ---------------------------------------------------------------------------
// DFMNET: 2-layer LSTM (B=2048, T=256, I=64, H=128) + 6-layer MLP head.
// R17: phase-fused pipeline on top of R16's full-chip layout (grid 148,
// 14/13 rows/CTA). Dependency analysis lets every activation window hide
// behind data-ready GEMM work:
//   P1: G1-x (32 ch)                      [x_t stored in P4(t-1)]
//   P2: act1 + G2-h2 (64 ch)              [h2_{t-1} ready]
//   P3: G2-h1 (64 ch) + x_{t+1} prefetch  [h1_t written in P2]
//   P4: act2 + x store + G1-h1 (64 ch)    [h1_t ready for step t+1]
// 4 barriers/step, no pure-MUFU phase; GEMM accumulators carry across one
// barrier (P4->P1, P2->P3). split-K 2 with separate layer-1/layer-2 gate
// buffers; thread = 4 cols x 7 row-pairs (acc[4][7], all LDS 8B-aligned).
// FFMA2/SMSP/step = 12544 (rt=3 RF-bank floor = 37.6K cyc/step).
// ---------------------------------------------------------------------------

#define T_SEQ    256
#define I_IN     64
#define H_HID    128
#define MROWS    14            // max rows per CTA
#define SLOT     16            // row-slot stride in xh (floats)
#define NTHREADS 256
#define KROWS    320           // xh rows: [x(64) | h1(128) | h2(128)]
#define GSTR     512           // gate-buffer row stride (floats)
#define BSTR     (MROWS * GSTR) // per-partial-buffer stride (floats)
#define NGRID    148

typedef unsigned long long ull;

// Weights: [chunk][j=0..1][cs=0..127][4 floats]; float4 j of strip cs =
// (c_{2j}k0, c_{2j}k1, c_{2j+1}k0, c_{2j+1}k1) for cols cs*4..cs*4+3,
// k = 2c, 2c+1. +1 zero-padded chunk so depth-1 prefetch never branches.
__device__ __align__(16) float g_Wt1[(96 + 1) * 1024];    // K=192 -> 96 chunks
__device__ __align__(16) float g_Wt2[(128 + 1) * 1024];   // K=256 -> 128 chunks
__device__ float g_b1[512];
__device__ float g_b2[512];

// ---- packed fp32x2 helpers ----
__device__ __forceinline__ ull fma2(ull a, ull b, ull c) {
    ull d;
    asm("fma.rn.f32x2 %0, %1, %2, %3;" : "=l"(d) : "l"(a), "l"(b), "l"(c));
    return d;
}
__device__ __forceinline__ void unpack2(ull v, float& lo, float& hi) {
    unsigned a, b;
    asm("mov.b64 {%0, %1}, %2;" : "=r"(a), "=r"(b) : "l"(v));
    lo = __uint_as_float(a); hi = __uint_as_float(b);
}
__device__ __forceinline__ ull dup2(float w) {
    ull r; unsigned u = __float_as_uint(w);
    asm("mov.b64 %0, {%1, %1};" : "=l"(r) : "r"(u));
    return r;
}

__device__ __forceinline__ float sigf(float v) {
    return __fdividef(1.f, 1.f + __expf(-v));
}
__device__ __forceinline__ float tanhf_fast(float v) {
    float z = fminf(fmaxf(v, -15.f), 15.f);
    float e = __expf(-2.f * z);
    return __fdividef(1.f - e, 1.f + e);
}

// ---------------------------------------------------------------------------
// Weight repack: [chunk][j][cs][f]
//   e = c*1024 + j*512 + cs*4 + f ; ci = 2j + (f>>1), s = f&1
//   g = cs*4 + ci ; k = 2c + s  (k >= K -> 0 pad)
// ---------------------------------------------------------------------------
__global__ void prep_kernel(const float* __restrict__ Wih1, const float* __restrict__ Whh1,
                            const float* __restrict__ bih1, const float* __restrict__ bhh1,
                            const float* __restrict__ Wih2, const float* __restrict__ Whh2,
                            const float* __restrict__ bih2, const float* __restrict__ bhh2)
{
    int tid = blockIdx.x * blockDim.x + threadIdx.x;
    int stride = gridDim.x * blockDim.x;
    if (tid < 512) {
        g_b1[tid] = bih1[tid] + bhh1[tid];
        g_b2[tid] = bih2[tid] + bhh2[tid];
    }
    for (int e = tid; e < 97 * 1024; e += stride) {
        int c = e >> 10, r = e & 1023;
        int j = r >> 9, cs = (r >> 2) & 127, f = r & 3;
        int ci = 2 * j + (f >> 1), s = f & 1;
        int g = cs * 4 + ci;
        int k = 2 * c + s;
        float w = 0.f;
        if (k < 192) w = (k < 64) ? Wih1[g * 64 + k] : Whh1[g * 128 + (k - 64)];
        g_Wt1[e] = w;
    }
    for (int e = tid; e < 129 * 1024; e += stride) {
        int c = e >> 10, r = e & 1023;
        int j = r >> 9, cs = (r >> 2) & 127, f = r & 3;
        int ci = 2 * j + (f >> 1), s = f & 1;
        int g = cs * 4 + ci;
        int k = 2 * c + s;
        float w = 0.f;
        if (k < 256) w = (k < 128) ? Wih2[g * 128 + k] : Whh2[g * 128 + (k - 128)];
        g_Wt2[e] = w;
    }
}

// ---------------------------------------------------------------------------
// Accumulator init: bias (kg==0) or zero.
// ---------------------------------------------------------------------------
__device__ __forceinline__ void init_acc(ull acc[4][7], const float* __restrict__ bias,
                                         int c0, bool add_bias)
{
    if (add_bias) {
#pragma unroll
        for (int ci = 0; ci < 4; ci++) {
            ull b = dup2(bias[c0 + ci]);
#pragma unroll
            for (int p = 0; p < 7; p++) acc[ci][p] = b;
        }
    } else {
#pragma unroll
        for (int ci = 0; ci < 4; ci++)
#pragma unroll
            for (int p = 0; p < 7; p++) acc[ci][p] = 0ull;
    }
}

// ---------------------------------------------------------------------------
// GEMM accumulate over chunk range [cb, cb+nc) into live acc[4][7].
// Thread: 4 cols (cs*4..+3) x 14 rows (7 f32x2 pairs at even slots 0..13).
// Per chunk: 2 coalesced LDG.128 (depth-1 ring), 8 broadcast LDS (6x128 +
// 2x64), 8 dup MOVs (alu), 56 FFMA2 (the rt=3 binder).
// ---------------------------------------------------------------------------
__device__ __forceinline__ void gemm_acc(ull acc[4][7], const float* __restrict__ Wt,
                                         const float* __restrict__ xh,   // [k][SLOT]
                                         int cb, int nc, int cs)
{
    const float4* Wp = (const float4*)Wt + cb * 256 + cs;
    float4 w0 = Wp[0], w1 = Wp[128];
    const float* xb = xh + cb * (2 * SLOT);

#pragma unroll 4
    for (int c = 0; c < nc; c++) {
        float4 n0 = Wp[256], n1 = Wp[384];   // prefetch next chunk (padded)
        Wp += 256;
        // rows 0..13 for k = 2c (qe*) and k = 2c+1 (qo*); warp-broadcast
        const ulonglong2* xe2 = (const ulonglong2*)xb;
        ulonglong2 ea = xe2[0], eb = xe2[1], ec = xe2[2];
        ull qe6 = ((const ull*)xb)[6];
        const float* xo = xb + SLOT;
        const ulonglong2* xo2 = (const ulonglong2*)xo;
        ulonglong2 oa = xo2[0], ob = xo2[1], oc = xo2[2];
        ull qo6 = ((const ull*)xo)[6];
        xb += 2 * SLOT;

        ull qe0 = ea.x, qe1 = ea.y, qe2 = eb.x, qe3 = eb.y, qe4 = ec.x, qe5 = ec.y;
        ull qo0 = oa.x, qo1 = oa.y, qo2 = ob.x, qo3 = ob.y, qo4 = oc.x, qo5 = oc.y;

        ull t;
        // col 0
        t = dup2(w0.x);
        acc[0][0] = fma2(t, qe0, acc[0][0]); acc[0][1] = fma2(t, qe1, acc[0][1]);
        acc[0][2] = fma2(t, qe2, acc[0][2]); acc[0][3] = fma2(t, qe3, acc[0][3]);
        acc[0][4] = fma2(t, qe4, acc[0][4]); acc[0][5] = fma2(t, qe5, acc[0][5]);
        acc[0][6] = fma2(t, qe6, acc[0][6]);
        t = dup2(w0.y);
        acc[0][0] = fma2(t, qo0, acc[0][0]); acc[0][1] = fma2(t, qo1, acc[0][1]);
        acc[0][2] = fma2(t, qo2, acc[0][2]); acc[0][3] = fma2(t, qo3, acc[0][3]);
        acc[0][4] = fma2(t, qo4, acc[0][4]); acc[0][5] = fma2(t, qo5, acc[0][5]);
        acc[0][6] = fma2(t, qo6, acc[0][6]);
        // col 1
        t = dup2(w0.z);
        acc[1][0] = fma2(t, qe0, acc[1][0]); acc[1][1] = fma2(t, qe1, acc[1][1]);
        acc[1][2] = fma2(t, qe2, acc[1][2]); acc[1][3] = fma2(t, qe3, acc[1][3]);
        acc[1][4] = fma2(t, qe4, acc[1][4]); acc[1][5] = fma2(t, qe5, acc[1][5]);
        acc[1][6] = fma2(t, qe6, acc[1][6]);
        t = dup2(w0.w);
        acc[1][0] = fma2(t, qo0, acc[1][0]); acc[1][1] = fma2(t, qo1, acc[1][1]);
        acc[1][2] = fma2(t, qo2, acc[1][2]); acc[1][3] = fma2(t, qo3, acc[1][3]);
        acc[1][4] = fma2(t, qo4, acc[1][4]); acc[1][5] = fma2(t, qo5, acc[1][5]);
        acc[1][6] = fma2(t, qo6, acc[1][6]);
        // col 2
        t = dup2(w1.x);
        acc[2][0] = fma2(t, qe0, acc[2][0]); acc[2][1] = fma2(t, qe1, acc[2][1]);
        acc[2][2] = fma2(t, qe2, acc[2][2]); acc[2][3] = fma2(t, qe3, acc[2][3]);
        acc[2][4] = fma2(t, qe4, acc[2][4]); acc[2][5] = fma2(t, qe5, acc[2][5]);
        acc[2][6] = fma2(t, qe6, acc[2][6]);
        t = dup2(w1.y);
        acc[2][0] = fma2(t, qo0, acc[2][0]); acc[2][1] = fma2(t, qo1, acc[2][1]);
        acc[2][2] = fma2(t, qo2, acc[2][2]); acc[2][3] = fma2(t, qo3, acc[2][3]);
        acc[2][4] = fma2(t, qo4, acc[2][4]); acc[2][5] = fma2(t, qo5, acc[2][5]);
        acc[2][6] = fma2(t, qo6, acc[2][6]);
        // col 3
        t = dup2(w1.z);
        acc[3][0] = fma2(t, qe0, acc[3][0]); acc[3][1] = fma2(t, qe1, acc[3][1]);
        acc[3][2] = fma2(t, qe2, acc[3][2]); acc[3][3] = fma2(t, qe3, acc[3][3]);
        acc[3][4] = fma2(t, qe4, acc[3][4]); acc[3][5] = fma2(t, qe5, acc[3][5]);
        acc[3][6] = fma2(t, qe6, acc[3][6]);
        t = dup2(w1.w);
        acc[3][0] = fma2(t, qo0, acc[3][0]); acc[3][1] = fma2(t, qo1, acc[3][1]);
        acc[3][2] = fma2(t, qo2, acc[3][2]); acc[3][3] = fma2(t, qo3, acc[3][3]);
        acc[3][4] = fma2(t, qo4, acc[3][4]); acc[3][5] = fma2(t, qo5, acc[3][5]);
        acc[3][6] = fma2(t, qo6, acc[3][6]);

        w0 = n0; w1 = n1;
    }
}

// Store acc to a gate partial buffer: 14 rows x 4 cols, one float4 per row.
__device__ __forceinline__ void sts_gates(ull acc[4][7], float* __restrict__ gbuf, int cs)
{
    const int c0 = cs * 4;
#pragma unroll
    for (int p = 0; p < 7; p++) {
        float la[4], ha[4];
#pragma unroll
        for (int ci = 0; ci < 4; ci++) unpack2(acc[ci][p], la[ci], ha[ci]);
        float* d0 = gbuf + (2 * p) * GSTR + c0;
        *(float4*)(d0)        = make_float4(la[0], la[1], la[2], la[3]);
        *(float4*)(d0 + GSTR) = make_float4(ha[0], ha[1], ha[2], ha[3]);
    }
}

// LSTM activation over one layer's gate buffer (2 partials); h -> hdst.
__device__ __forceinline__ void act_layer(const float* __restrict__ gb,
                                          float* __restrict__ cst,
                                          float* __restrict__ hdst,
                                          int myrows, int tid)
{
#pragma unroll
    for (int p = 0; p < 7; p++) {
        int idx = tid + p * NTHREADS;          // 0..1791
        int r = idx >> 7, j = idx & 127;
        if (r < myrows) {
            const float* g0 = gb + r * GSTR + j;
            float pi = g0[0]   + g0[BSTR];
            float pf = g0[128] + g0[BSTR + 128];
            float pg = g0[256] + g0[BSTR + 256];
            float po = g0[384] + g0[BSTR + 384];
            float iv = sigf(pi);
            float fv = sigf(pf);
            float gv = tanhf_fast(pg);
            float ov = sigf(po);
            float c = fv * cst[idx] + iv * gv;
            cst[idx] = c;
            hdst[j * SLOT + r] = ov * tanhf_fast(c);
        }
    }
}

// Small MLP layer over the CTA's rows (head only; negligible cost)
__device__ __forceinline__ void mlp_layer(const float* __restrict__ vin, int Din,
                                          const float* __restrict__ W, const float* __restrict__ b,
                                          float* __restrict__ vout, int Dout,
                                          bool relu, int tid, int myrows)
{
    for (int e = tid; e < myrows * Dout; e += NTHREADS) {
        int r = e / Dout, o = e - r * Dout;
        const float* w = W + o * Din;
        const float* vi = vin + r * Din;
        float s = b[o];
        for (int i = 0; i < Din; i += 4) {
            s += w[i] * vi[i] + w[i + 1] * vi[i + 1] + w[i + 2] * vi[i + 2] + w[i + 3] * vi[i + 3];
        }
        vout[e] = relu ? fmaxf(s, 0.f) : s;
    }
    __syncthreads();
}

// ---------------------------------------------------------------------------
__global__ void __launch_bounds__(NTHREADS, 1)
dfmnet_main(const float* __restrict__ x,
            const float* __restrict__ Wk0, const float* __restrict__ bk0,
            const float* __restrict__ Wk1, const float* __restrict__ bk1,
            const float* __restrict__ Wk2, const float* __restrict__ bk2,
            const float* __restrict__ Wk3, const float* __restrict__ bk3,
            const float* __restrict__ Wk4, const float* __restrict__ bk4,
            const float* __restrict__ Wk5, const float* __restrict__ bk5,
            float* __restrict__ out, int Bn)
{
    extern __shared__ float sm[];
    float* xh    = sm;                         // [KROWS][SLOT]        5120 f
    float* gbuf1 = sm + KROWS * SLOT;          // 2 partials [14][GSTR] 14336 f
    float* gbuf2 = gbuf1 + 2 * BSTR;           // 2 partials            14336 f
    float* c1s   = gbuf2 + 2 * BSTR;           // [14*128]              1792 f
    float* c2s   = c1s + MROWS * H_HID;        // [14*128]              1792 f

    const int tid = threadIdx.x;
    const int kg  = tid >> 7;             // k-group 0/1 (4 warps each)
    const int cs  = tid & 127;            // col-strip: cols cs*4..cs*4+3
    const int c0  = cs * 4;
    const int bx  = blockIdx.x;

    // row split: nhi CTAs of rhi rows, rest rhi-1 rows
    const int rhi  = (Bn + NGRID - 1) / NGRID;
    const int nhi  = Bn - NGRID * (rhi - 1);
    const int myrows = (bx < nhi) ? rhi : (rhi - 1);
    const int b0     = (bx < nhi) ? bx * rhi : nhi * rhi + (bx - nhi) * (rhi - 1);

    for (int e = tid; e < KROWS * SLOT; e += NTHREADS) xh[e] = 0.f;
    for (int e = tid; e < MROWS * H_HID; e += NTHREADS) { c1s[e] = 0.f; c2s[e] = 0.f; }

    const float* xbase = x + (size_t)b0 * T_SEQ * I_IN;
    float* my1 = gbuf1 + kg * BSTR;
    float* my2 = gbuf2 + kg * BSTR;

    // prologue: store x_0 into xh rows [0,64)
    for (int e = tid; e < myrows * I_IN; e += NTHREADS) {
        int r = e >> 6, k = e & 63;
        xh[k * SLOT + r] = xbase[(size_t)r * (T_SEQ * I_IN) + k];
    }
    __syncthreads();

    // G1 accumulator carries across P4 -> P1; prologue: h1_{-1} = 0, so
    // the G1-h1 half contributes nothing -> acc starts at bias only.
    ull acc[4][7];
    init_acc(acc, g_b1, c0, kg == 0);

    for (int t = 0; t < T_SEQ; t++) {
        // P1: finish G1 with x chunks [kg*16, +16); publish layer-1 gates
        gemm_acc(acc, g_Wt1, xh, kg * 16, 16, cs);
        sts_gates(acc, my1, cs);
        __syncthreads();

        // P2: act1 (writes h1_t rows [64,192)) + G2-h2 chunks [64+kg*32,+32)
        act_layer(gbuf1, c1s, xh + 64 * SLOT, myrows, tid);
        init_acc(acc, g_b2, c0, kg == 0);
        gemm_acc(acc, g_Wt2, xh + 64 * SLOT, 64 + kg * 32, 32, cs);
        __syncthreads();

        // P3: x_{t+1} prefetch + G2-h1 chunks [kg*32,+32); publish layer-2
        float xr[4];
        {
            int tn = (t + 1 < T_SEQ) ? (t + 1) : (T_SEQ - 1);
#pragma unroll
            for (int q = 0; q < 4; q++) {
                int e = tid + q * NTHREADS;
                int r = e >> 6;
                xr[q] = (r < myrows)
                    ? xbase[(size_t)r * (T_SEQ * I_IN) + (size_t)tn * I_IN + (e & 63)]
                    : 0.f;
            }
        }
        gemm_acc(acc, g_Wt2, xh + 64 * SLOT, kg * 32, 32, cs);
        sts_gates(acc, my2, cs);
        __syncthreads();

        // P4: act2 (writes h2_t rows [192,320)) + store x_{t+1} +
        //     G1-h1 chunks [32+kg*32,+32) for step t+1 (reads h1_t)
        act_layer(gbuf2, c2s, xh + 192 * SLOT, myrows, tid);
#pragma unroll
        for (int q = 0; q < 4; q++) {
            int e = tid + q * NTHREADS;
            int r = e >> 6;
            if (r < myrows) xh[(e & 63) * SLOT + r] = xr[q];
        }
        init_acc(acc, g_b1, c0, kg == 0);
        gemm_acc(acc, g_Wt1, xh, 32 + kg * 32, 32, cs);
        __syncthreads();
    }

    // ---- outputs: tuple (y, h2, r) flattened ----
    float* out_y  = out;                              // [Bn][64]
    float* out_h2 = out + (size_t)Bn * 64;            // [Bn][128]
    float* out_r  = out + (size_t)Bn * 192;           // [Bn][192]

    float* va = gbuf1;               // [14][192]
    float* vb = gbuf1 + MROWS * 192; // [14][128]
    float* vc = vb + MROWS * 128;    // [14][128]
    for (int e = tid; e < myrows * 192; e += NTHREADS) {
        int r = e / 192, j = e - r * 192;
        // xh x-rows hold x_{T-1} (last prefetch clamped); h2 rows final h2
        float v = (j < 128) ? xh[(192 + j) * SLOT + r] : xh[(j - 128) * SLOT + r];
        va[e] = v;
        out_r[(size_t)(b0 + r) * 192 + j] = v;
        if (j < 128) out_h2[(size_t)(b0 + r) * 128 + j] = v;
    }
    __syncthreads();

    mlp_layer(va, 192, Wk0, bk0, vb, 128, true, tid, myrows);
    mlp_layer(vb, 128, Wk1, bk1, vc, 128, true, tid, myrows);
    mlp_layer(vc, 128, Wk2, bk2, vb, 128, true, tid, myrows);
    mlp_layer(vb, 128, Wk3, bk3, vc, 128, true, tid, myrows);
    mlp_layer(vc, 128, Wk4, bk4, vb, 128, true, tid, myrows);

    for (int e = tid; e < myrows * 64; e += NTHREADS) {
        int r = e >> 6, o = e & 63;
        const float* w = Wk5 + o * 128;
        const float* vi = vb + r * 128;
        float s = bk5[o];
        for (int i = 0; i < 128; i += 4) {
            s += w[i] * vi[i] + w[i + 1] * vi[i + 1] + w[i + 2] * vi[i + 2] + w[i + 3] * vi[i + 3];
        }
        out_y[(size_t)(b0 + r) * 64 + o] = s;
    }
}

// ---------------------------------------------------------------------------
extern "C" void kernel_launch(void* const* d_in, const int* in_sizes, int n_in,
                              void* d_out, int out_size)
{
    const float* x    = (const float*)d_in[0];
    const float* Wih1 = (const float*)d_in[1];
    const float* Whh1 = (const float*)d_in[2];
    const float* bih1 = (const float*)d_in[3];
    const float* bhh1 = (const float*)d_in[4];
    const float* Wih2 = (const float*)d_in[5];
    const float* Whh2 = (const float*)d_in[6];
    const float* bih2 = (const float*)d_in[7];
    const float* bhh2 = (const float*)d_in[8];
    const float* Wk0 = (const float*)d_in[9];   const float* bk0 = (const float*)d_in[10];
    const float* Wk1 = (const float*)d_in[11];  const float* bk1 = (const float*)d_in[12];
    const float* Wk2 = (const float*)d_in[13];  const float* bk2 = (const float*)d_in[14];
    const float* Wk3 = (const float*)d_in[15];  const float* bk3 = (const float*)d_in[16];
    const float* Wk4 = (const float*)d_in[17];  const float* bk4 = (const float*)d_in[18];
    const float* Wk5 = (const float*)d_in[19];  const float* bk5 = (const float*)d_in[20];

    int Bn = in_sizes[0] / (T_SEQ * I_IN);
    // xh + 2x2 gate partials + c1 + c2
    int smem_bytes = (KROWS * SLOT + 4 * BSTR + 2 * MROWS * H_HID) * (int)sizeof(float); // 149504 B

    cudaFuncSetAttribute(dfmnet_main, cudaFuncAttributeMaxDynamicSharedMemorySize, smem_bytes);

    prep_kernel<<<208, 256>>>(Wih1, Whh1, bih1, bhh1, Wih2, Whh2, bih2, bhh2);
    dfmnet_main<<<NGRID, NTHREADS, smem_bytes>>>(
        x, Wk0, bk0, Wk1, bk1, Wk2, bk2, Wk3, bk3, Wk4, bk4, Wk5, bk5,
        (float*)d_out, Bn);
}